// round 8
// baseline (speedup 1.0000x reference)
#include <cuda_runtime.h>
#include <cuda_fp16.h>
#include <cstdint>

// Problem: B=128, L_IM=50, L_S=40, D=1024
// im = im_set[:,1:,:]  -> il = im_len-1 valid rows (9..49), stored padded to 64
// s  = s_seq[:,1:-2,:] -> sl = s_len-3  valid rows (7..37), stored padded to 40
// Batches are processed in length-sorted order (g_ordI / g_ordJ) so the
// per-CTA warp trim masks are balanced; trimmed regions are exact 0
// (zfill cp.async + skipped MMAs) = reference's masked zeros.
#define NBATCH 128
#define DDIM   1024
#define AROWS  64
#define SROWS  40

__device__ __align__(1024) __half g_A[(size_t)NBATCH * AROWS * DDIM];  // 16 MB
__device__ __align__(1024) __half g_S[(size_t)NBATCH * SROWS * DDIM];  // 10 MB
__device__ int g_ordI[NBATCH];   // sorted position -> original i
__device__ int g_ordJ[NBATCH];   // sorted position -> original j

// ---------------- helpers ----------------
__device__ __forceinline__ uint32_t smem_u32(const void* p) {
    uint32_t a;
    asm("{ .reg .u64 t; cvta.to.shared.u64 t, %1; cvt.u32.u64 %0, t; }" : "=r"(a) : "l"(p));
    return a;
}

// cp.async with runtime src-size: 16 = real load, 0 = zero-fill (no L2 read)
#define CP_ASYNC16Z(dst, src, sz) \
    asm volatile("cp.async.cg.shared.global [%0], [%1], 16, %2;" \
                 :: "r"(dst), "l"(src), "r"(sz))
#define CP_COMMIT() asm volatile("cp.async.commit_group;" ::: "memory")
#define CP_WAIT2()  asm volatile("cp.async.wait_group 2;" ::: "memory")

#define LDSM4(r, addr) \
    asm volatile("ldmatrix.sync.aligned.m8n8.x4.shared.b16 {%0,%1,%2,%3}, [%4];" \
                 : "=r"((r)[0]), "=r"((r)[1]), "=r"((r)[2]), "=r"((r)[3]) : "r"(addr))

#define MMA16816(c, a, b0, b1) \
    asm volatile("mma.sync.aligned.m16n8k16.row.col.f32.f16.f16.f32 " \
                 "{%0,%1,%2,%3},{%4,%5,%6,%7},{%8,%9},{%0,%1,%2,%3};" \
                 : "+f"((c)[0]), "+f"((c)[1]), "+f"((c)[2]), "+f"((c)[3]) \
                 : "r"((a)[0]), "r"((a)[1]), "r"((a)[2]), "r"((a)[3]), "r"(b0), "r"(b1))

__device__ __forceinline__ float wsum(float v) {
#pragma unroll
    for (int m = 16; m > 0; m >>= 1) v += __shfl_xor_sync(0xffffffffu, v, m);
    return v;
}

// ------------- sort: rank batches by length (stable) -------------
__global__ void sort_kernel(const int* __restrict__ im_len, const int* __restrict__ s_len) {
    __shared__ int li[NBATCH], lj[NBATCH];
    int t = threadIdx.x;
    li[t] = im_len[t];
    lj[t] = s_len[t];
    __syncthreads();
    int vi = li[t], vj = lj[t];
    int ri = 0, rj = 0;
#pragma unroll 8
    for (int k = 0; k < NBATCH; k++) {
        ri += (int)((li[k] < vi) | ((li[k] == vi) & (k < t)));
        rj += (int)((lj[k] < vj) | ((lj[k] == vj) & (k < t)));
    }
    g_ordI[ri] = t;
    g_ordJ[rj] = t;
}

// ------------- conversion: fp32 -> fp16, valid rows only -------------
__global__ void convA_kernel(const float* __restrict__ im, const int* __restrict__ im_len) {
    int u = blockIdx.x * blockDim.x + threadIdx.x;        // < 128*64*128
    int i  = u >> 13;
    int r  = (u >> 7) & 63;
    int d0 = (u & 127) << 3;
    int L = im_len[i] - 1;
    if (r >= L || r >= 49) return;                        // rows never read (zfill)
    const float* src = im + ((size_t)i * 50 + r + 1) * DDIM + d0;
    float4 f0 = ((const float4*)src)[0];
    float4 f1 = ((const float4*)src)[1];
    union { uint4 v; __half2 h[4]; } pk;
    pk.h[0] = __float22half2_rn(make_float2(f0.x, f0.y));
    pk.h[1] = __float22half2_rn(make_float2(f0.z, f0.w));
    pk.h[2] = __float22half2_rn(make_float2(f1.x, f1.y));
    pk.h[3] = __float22half2_rn(make_float2(f1.z, f1.w));
    *((uint4*)(g_A + ((size_t)i * AROWS + r) * DDIM + d0)) = pk.v;
}

__global__ void convS_kernel(const float* __restrict__ s, const int* __restrict__ s_len) {
    int u = blockIdx.x * blockDim.x + threadIdx.x;        // < 128*40*128
    int i   = u / (SROWS * 128);
    int rem = u - i * (SROWS * 128);
    int r  = rem >> 7;
    int d0 = (rem & 127) << 3;
    int L = s_len[i] - 3;
    if (r >= L || r >= 37) return;
    const float* src = s + ((size_t)i * 40 + r + 1) * DDIM + d0;
    float4 f0 = ((const float4*)src)[0];
    float4 f1 = ((const float4*)src)[1];
    union { uint4 v; __half2 h[4]; } pk;
    pk.h[0] = __float22half2_rn(make_float2(f0.x, f0.y));
    pk.h[1] = __float22half2_rn(make_float2(f0.z, f0.w));
    pk.h[2] = __float22half2_rn(make_float2(f1.x, f1.y));
    pk.h[3] = __float22half2_rn(make_float2(f1.z, f1.w));
    *((uint4*)(g_S + ((size_t)i * SROWS + r) * DDIM + d0)) = pk.v;
}

// ------------- GEMM + fused masked max/sum epilogue -------------
// CTA: 512 threads, tile M=128 (2 sorted i), N=320 (8 sorted j x 40),
// K=1024 in 16 chunks of 64. Warp grid 4(m) x 4(n): warp tile 32 x 80
// (the proven R6 shape). Trimming is warp-uniform and balanced by the sort.
#define PITCH     144
#define ASTAGE    18432              // 128*144
#define STAGE_SZ  64512              // ASTAGE + 320*144
#define SMEM_BYTES (128 + STAGE_SZ * 3)
#define CPITCH    326                // even -> float2-aligned; 326*4 % 128 = 24

__global__ void __launch_bounds__(512, 1) align_gemm_kernel(
        const int* __restrict__ im_len, const int* __restrict__ s_len,
        float* __restrict__ out) {
    extern __shared__ __align__(16) char smem[];
    const int tid  = threadIdx.x;
    const int lane = tid & 31;
    const int wid  = tid >> 5;
    const int wm   = wid & 3;        // M offset wm*32
    const int wn   = wid >> 2;       // N offset wn*80
    const int jb = blockIdx.x;       // 0..15
    const int ib = blockIdx.y;       // 0..63
    const uint32_t sbase = smem_u32(smem) + 128;

    // ---- permuted batches & lengths ----
    const int oi0 = g_ordI[ib * 2 + 0];
    const int oi1 = g_ordI[ib * 2 + 1];
    const int il0 = __ldg(&im_len[oi0]) - 1;
    const int il1 = __ldg(&im_len[oi1]) - 1;

    // ---- warp compute masks (warp-uniform; balanced thanks to sort) ----
    const int il_w = (wm >= 2) ? il1 : il0;          // rows wm*32 belong to slot wm>>1
    const bool mt_act0 = ((wm & 1) * 32)      < il_w;
    const bool mt_act1 = ((wm & 1) * 32 + 16) < il_w;
    const int wj0 = g_ordJ[jb * 8 + wn * 2 + 0];
    const int wj1 = g_ordJ[jb * 8 + wn * 2 + 1];
    const int slw0 = __ldg(&s_len[wj0]) - 3;
    const int slw1 = __ldg(&s_len[wj1]) - 3;
    uint32_t ntm = 0;
#pragma unroll
    for (int nt = 0; nt < 10; nt++) {
        int sj = (nt < 5) ? slw0 : slw1;
        if (((nt % 5) * 8) < sj) ntm |= (1u << nt);
    }

    // ---- per-thread load setup (advance src by 128B per kt) ----
    const char* srcA[2]; uint32_t dstA[2], szA[2];
#pragma unroll
    for (int q = 0; q < 2; q++) {
        int idx = tid + q * 512, row = idx >> 3, cc = idx & 7;
        int slot = row >> 6, r = row & 63;
        int ob = slot ? oi1 : oi0;
        int il = slot ? il1 : il0;
        szA[q] = (r < il) ? 16u : 0u;
        srcA[q] = (const char*)(g_A + ((size_t)ob * AROWS + r) * DDIM) + cc * 16;
        dstA[q] = sbase + row * PITCH + cc * 16;
    }
    const char* srcB[5]; uint32_t dstB[5], szB[5];
#pragma unroll
    for (int q = 0; q < 5; q++) {
        int idx = tid + q * 512, row = idx >> 3, cc = idx & 7;
        int jslot = (row * 205) >> 13;          // row/40 for row<320
        int w = row - jslot * 40;
        int obj = g_ordJ[jb * 8 + jslot];
        int slj = __ldg(&s_len[obj]) - 3;
        szB[q] = (w < slj) ? 16u : 0u;
        srcB[q] = (const char*)(g_S + ((size_t)obj * SROWS + w) * DDIM) + cc * 16;
        dstB[q] = sbase + ASTAGE + row * PITCH + cc * 16;
    }

    // ldmatrix lane addresses
    const int quad = lane >> 3, r8 = lane & 7;
    const uint32_t a_lane = (uint32_t)((wm * 32 + (quad & 1) * 8 + r8) * PITCH
                                       + (quad >> 1) * 16);
    const uint32_t b_lane = (uint32_t)(ASTAGE
                                       + (wn * 80 + (quad >> 1) * 8 + r8) * PITCH
                                       + (quad & 1) * 16);

    float c[2][10][4];
#pragma unroll
    for (int mt = 0; mt < 2; mt++)
#pragma unroll
        for (int nt = 0; nt < 10; nt++)
#pragma unroll
            for (int q = 0; q < 4; q++) c[mt][nt][q] = 0.0f;

    // ---- prologue: 3 stages in flight ----
#pragma unroll
    for (int p = 0; p < 3; p++) {
        uint32_t so = (uint32_t)(p * STAGE_SZ), ko = (uint32_t)(p * 128);
#pragma unroll
        for (int q = 0; q < 2; q++) CP_ASYNC16Z(dstA[q] + so, srcA[q] + ko, szA[q]);
#pragma unroll
        for (int q = 0; q < 5; q++) CP_ASYNC16Z(dstB[q] + so, srcB[q] + ko, szB[q]);
        CP_COMMIT();
    }

    int stg = 0;
#pragma unroll 1
    for (int kt = 0; kt < 16; kt++) {
        CP_WAIT2();
        __syncthreads();

        const uint32_t stga = sbase + stg * STAGE_SZ;
#pragma unroll
        for (int step = 0; step < 4; step++) {
            uint32_t areg[2][4], breg[5][4];
            if (mt_act0) LDSM4(areg[0], stga + a_lane + step * 32);
            if (mt_act1) LDSM4(areg[1], stga + a_lane + 16 * PITCH + step * 32);
#pragma unroll
            for (int nn = 0; nn < 5; nn++)
                if ((ntm >> (2 * nn)) & 3)
                    LDSM4(breg[nn], stga + b_lane + nn * 16 * PITCH + step * 32);
#pragma unroll
            for (int nt = 0; nt < 10; nt++) {
                if ((ntm >> nt) & 1) {
                    if (mt_act0)
                        MMA16816(c[0][nt], areg[0], breg[nt >> 1][(nt & 1) * 2],
                                 breg[nt >> 1][(nt & 1) * 2 + 1]);
                    if (mt_act1)
                        MMA16816(c[1][nt], areg[1], breg[nt >> 1][(nt & 1) * 2],
                                 breg[nt >> 1][(nt & 1) * 2 + 1]);
                }
            }
        }
        __syncthreads();   // all warps done reading stage stg before overwrite
        if (kt + 3 < 16) {
            uint32_t so = (uint32_t)(stg * STAGE_SZ), ko = (uint32_t)((kt + 3) * 128);
#pragma unroll
            for (int q = 0; q < 2; q++) CP_ASYNC16Z(dstA[q] + so, srcA[q] + ko, szA[q]);
#pragma unroll
            for (int q = 0; q < 5; q++) CP_ASYNC16Z(dstB[q] + so, srcB[q] + ko, szB[q]);
        }
        CP_COMMIT();       // empty commits at tail keep wait_group semantics
        stg = (stg + 1 == 3) ? 0 : stg + 1;
    }
    __syncthreads();       // compute done; smem reused for C

    // ---- store C tile to smem: [128][CPITCH] floats ----
    float* C   = (float*)smem;
    float* acc = (float*)(smem + 128 * CPITCH * 4);   // 16 floats (2 i x 8 j)
    float* red = acc + 16;                            // 2*320 floats
    if (tid < 16) acc[tid] = 0.0f;
#pragma unroll
    for (int mt = 0; mt < 2; mt++)
#pragma unroll
        for (int nt = 0; nt < 10; nt++) {
            int row = wm * 32 + mt * 16 + (lane >> 2);
            int col = wn * 80 + nt * 8 + (lane & 3) * 2;
            *(float2*)&C[row * CPITCH + col]       = make_float2(c[mt][nt][0], c[mt][nt][1]);
            *(float2*)&C[(row + 8) * CPITCH + col] = make_float2(c[mt][nt][2], c[mt][nt][3]);
        }
    __syncthreads();

    // ---- row part: row r (<49 per slot), max over w<37 per j-block, summed ----
    {
        int row = tid & 127;
        int jpair = tid >> 7;              // 2 j-blocks per thread
        int il = row >> 6, ro = row & 63;
        const float* Cr = &C[row * CPITCH];
#pragma unroll
        for (int jj = 0; jj < 2; jj++) {
            int jblock = jpair * 2 + jj;
            float rm = Cr[jblock * 40];
#pragma unroll
            for (int w = 1; w < 37; w++) rm = fmaxf(rm, Cr[jblock * 40 + w]);
            float rs = wsum((ro < 49) ? rm : 0.0f);
            if (lane == 0) atomicAdd(&acc[il * 8 + jblock], rs);
        }
    }
    // ---- col part: col w (<37 per j-block), max over r<49 ----
    if (tid < 320) {
        int w = tid % 40;
#pragma unroll
        for (int il = 0; il < 2; il++) {
            const float* Cc = &C[il * 64 * CPITCH + tid];
            float cm = Cc[0];
#pragma unroll
            for (int r = 1; r < 49; r++) cm = fmaxf(cm, Cc[r * CPITCH]);
            red[il * 320 + tid] = (w < 37) ? cm : 0.0f;
        }
    }
    __syncthreads();
    if (tid < 16) {
        int il = tid >> 3, jj = tid & 7;
        float sum = acc[tid];
        const float* rp = &red[il * 320 + jj * 40];
#pragma unroll
        for (int w = 0; w < 37; w++) sum += rp[w];
        int oi = il ? oi1 : oi0;
        int oj = g_ordJ[jb * 8 + jj];
        out[oi * NBATCH + oj] = sum;
    }
}

extern "C" void kernel_launch(void* const* d_in, const int* in_sizes, int n_in,
                              void* d_out, int out_size) {
    (void)in_sizes; (void)n_in; (void)out_size;
    const float* im   = (const float*)d_in[0];
    const float* s    = (const float*)d_in[1];
    const int* im_len = (const int*)d_in[2];
    const int* s_len  = (const int*)d_in[3];
    float* out = (float*)d_out;

    sort_kernel<<<1, 128>>>(im_len, s_len);
    convA_kernel<<<4096, 256>>>(im, im_len);
    convS_kernel<<<2560, 256>>>(s, s_len);

    cudaFuncSetAttribute(align_gemm_kernel,
                         cudaFuncAttributeMaxDynamicSharedMemorySize, SMEM_BYTES);
    dim3 grid(16, 64);
    align_gemm_kernel<<<grid, 512, SMEM_BYTES>>>(im_len, s_len, out);
}

// round 9
// speedup vs baseline: 1.4993x; 1.4993x over previous
#include <cuda_runtime.h>
#include <cuda_fp16.h>
#include <cstdint>

// Problem: B=128, L_IM=50, L_S=40, D=1024
// im = im_set[:,1:,:]  -> il = im_len-1 valid rows (9..49)
// s  = s_seq[:,1:-2,:] -> sl = s_len-3  valid rows (7..37)
// Batches are bin-packed (whole) into dense GEMM tiles:
//   M: ceil(il/16) x 16-row fragments, 8 per 128-row tile  (<= 64 tiles)
//   N: ceil(sl/8)  x 8-col blocks,   40 per 320-col tile  (<= 16 tiles)
// Mainloop is fully dense (no masks). Pad rows/cols inside rounded
// fragments are exact zeros via cp.async zfill.
#define NBATCH 128
#define DDIM   1024
#define AROWS  64
#define SROWS  40

__device__ __align__(1024) __half g_A[(size_t)NBATCH * AROWS * DDIM];  // 16 MB
__device__ __align__(1024) __half g_S[(size_t)NBATCH * SROWS * DDIM];  // 10 MB

// ---- packing plan ----
__device__ int g_TM, g_TN;
__device__ int g_fB[64 * 8],  g_fR[64 * 8];    // M tile fragment -> batch, row base
__device__ int g_mN[64], g_mB[64 * 8], g_mRS[64 * 8], g_mIL[64 * 8];
__device__ int g_bJ[16 * 40], g_bW[16 * 40];   // N tile block -> batch, w base
__device__ int g_nN[16], g_nB[16 * 40], g_nCS[16 * 40], g_nSL[16 * 40];

// ---------------- helpers ----------------
__device__ __forceinline__ uint32_t smem_u32(const void* p) {
    uint32_t a;
    asm("{ .reg .u64 t; cvta.to.shared.u64 t, %1; cvt.u32.u64 %0, t; }" : "=r"(a) : "l"(p));
    return a;
}

#define CP_ASYNC16Z(dst, src, sz) \
    asm volatile("cp.async.cg.shared.global [%0], [%1], 16, %2;" \
                 :: "r"(dst), "l"(src), "r"(sz))
#define CP_COMMIT() asm volatile("cp.async.commit_group;" ::: "memory")
#define CP_WAIT2()  asm volatile("cp.async.wait_group 2;" ::: "memory")

#define LDSM4(r, addr) \
    asm volatile("ldmatrix.sync.aligned.m8n8.x4.shared.b16 {%0,%1,%2,%3}, [%4];" \
                 : "=r"((r)[0]), "=r"((r)[1]), "=r"((r)[2]), "=r"((r)[3]) : "r"(addr))

#define MMA16816(c, a, b0, b1) \
    asm volatile("mma.sync.aligned.m16n8k16.row.col.f32.f16.f16.f32 " \
                 "{%0,%1,%2,%3},{%4,%5,%6,%7},{%8,%9},{%0,%1,%2,%3};" \
                 : "+f"((c)[0]), "+f"((c)[1]), "+f"((c)[2]), "+f"((c)[3]) \
                 : "r"((a)[0]), "r"((a)[1]), "r"((a)[2]), "r"((a)[3]), "r"(b0), "r"(b1))

// ------------- planner: bin-pack batches into tiles (1 thread) -------------
__global__ void plan_kernel(const int* __restrict__ im_len, const int* __restrict__ s_len) {
    if (threadIdx.x != 0 || blockIdx.x != 0) return;
    // ---- M side ----
    for (int t = 0; t < 64; t++) {
        g_mN[t] = 0;
        for (int f = 0; f < 8; f++) g_fB[t * 8 + f] = -1;
    }
    int tm = 0, used = 0;
    for (int f = 4; f >= 1; f--) {
        for (int i = 0; i < NBATCH; i++) {
            int il = im_len[i] - 1;
            il = il < 1 ? 1 : (il > 49 ? 49 : il);
            int fr = (il + 15) >> 4;
            if (fr != f) continue;
            if (used + fr > 8) { tm++; used = 0; }
            int slot = g_mN[tm]++;
            g_mB[tm * 8 + slot]  = i;
            g_mRS[tm * 8 + slot] = used * 16;
            g_mIL[tm * 8 + slot] = il;
            for (int k = 0; k < fr; k++) {
                g_fB[tm * 8 + used + k] = i;
                g_fR[tm * 8 + used + k] = k * 16;
            }
            used += fr;
        }
    }
    g_TM = tm + (used > 0 ? 1 : 0);
    // ---- N side ----
    for (int t = 0; t < 16; t++) {
        g_nN[t] = 0;
        for (int b = 0; b < 40; b++) g_bJ[t * 40 + b] = -1;
    }
    int tn = 0; used = 0;
    for (int f = 5; f >= 1; f--) {
        for (int j = 0; j < NBATCH; j++) {
            int sl = s_len[j] - 3;
            sl = sl < 1 ? 1 : (sl > 37 ? 37 : sl);
            int bl = (sl + 7) >> 3;
            if (bl != f) continue;
            if (used + bl > 40) { tn++; used = 0; }
            int slot = g_nN[tn]++;
            g_nB[tn * 40 + slot]  = j;
            g_nCS[tn * 40 + slot] = used * 8;
            g_nSL[tn * 40 + slot] = sl;
            for (int k = 0; k < bl; k++) {
                g_bJ[tn * 40 + used + k] = j;
                g_bW[tn * 40 + used + k] = k * 8;
            }
            used += bl;
        }
    }
    g_TN = tn + (used > 0 ? 1 : 0);
}

// ------------- conversion: fp32 -> fp16, valid rows only -------------
__global__ void convA_kernel(const float* __restrict__ im, const int* __restrict__ im_len) {
    int u = blockIdx.x * blockDim.x + threadIdx.x;        // < 128*64*128
    int i  = u >> 13;
    int r  = (u >> 7) & 63;
    int d0 = (u & 127) << 3;
    int L = im_len[i] - 1;
    if (r >= L || r >= 49) return;                        // rows never read (zfill)
    const float* src = im + ((size_t)i * 50 + r + 1) * DDIM + d0;
    float4 f0 = ((const float4*)src)[0];
    float4 f1 = ((const float4*)src)[1];
    union { uint4 v; __half2 h[4]; } pk;
    pk.h[0] = __float22half2_rn(make_float2(f0.x, f0.y));
    pk.h[1] = __float22half2_rn(make_float2(f0.z, f0.w));
    pk.h[2] = __float22half2_rn(make_float2(f1.x, f1.y));
    pk.h[3] = __float22half2_rn(make_float2(f1.z, f1.w));
    *((uint4*)(g_A + ((size_t)i * AROWS + r) * DDIM + d0)) = pk.v;
}

__global__ void convS_kernel(const float* __restrict__ s, const int* __restrict__ s_len) {
    int u = blockIdx.x * blockDim.x + threadIdx.x;        // < 128*40*128
    int i   = u / (SROWS * 128);
    int rem = u - i * (SROWS * 128);
    int r  = rem >> 7;
    int d0 = (rem & 127) << 3;
    int L = s_len[i] - 3;
    if (r >= L || r >= 37) return;
    const float* src = s + ((size_t)i * 40 + r + 1) * DDIM + d0;
    float4 f0 = ((const float4*)src)[0];
    float4 f1 = ((const float4*)src)[1];
    union { uint4 v; __half2 h[4]; } pk;
    pk.h[0] = __float22half2_rn(make_float2(f0.x, f0.y));
    pk.h[1] = __float22half2_rn(make_float2(f0.z, f0.w));
    pk.h[2] = __float22half2_rn(make_float2(f1.x, f1.y));
    pk.h[3] = __float22half2_rn(make_float2(f1.z, f1.w));
    *((uint4*)(g_S + ((size_t)i * SROWS + r) * DDIM + d0)) = pk.v;
}

// ------------- dense packed GEMM + per-pair masked max/sum epilogue -------------
// CTA: 512 threads, tile M=128 x N=320, K=1024 in 16 chunks of 64.
// Warp grid 4(m) x 4(n): warp tile 32 x 80 (the proven R6 mainloop, unmodified).
#define PITCH     144
#define ASTAGE    18432              // 128*144
#define STAGE_SZ  64512              // ASTAGE + 320*144
#define CPITCH    326                // even -> float2-aligned; 326*4 % 128 = 24
// epilogue: C (128*CPITCH) + RM (128*40) + CM (8*320) = 197632 B  (> mainloop 193664)
#define SMEM_BYTES 197632

__global__ void __launch_bounds__(512, 1) align_gemm_kernel(
        const int* __restrict__ im_len, const int* __restrict__ s_len,
        float* __restrict__ out) {
    const int jb = blockIdx.x;       // N tile
    const int ib = blockIdx.y;       // M tile
    if (ib >= g_TM || jb >= g_TN) return;

    extern __shared__ __align__(16) char smem[];
    const int tid  = threadIdx.x;
    const int lane = tid & 31;
    const int wid  = tid >> 5;
    const int wm   = wid & 3;        // M offset wm*32
    const int wn   = wid >> 2;       // N offset wn*80
    const uint32_t sbase = smem_u32(smem) + 128;

    // ---- per-thread load setup (advance src by 128B per kt) ----
    const char* srcA[2]; uint32_t dstA[2], szA[2];
#pragma unroll
    for (int q = 0; q < 2; q++) {
        int idx = tid + q * 512, row = idx >> 3, cc = idx & 7;
        int f = row >> 4;
        int b = g_fB[ib * 8 + f];
        int r = g_fR[ib * 8 + f] + (row & 15);
        int il = (b >= 0) ? (__ldg(&im_len[b]) - 1) : 0;
        szA[q] = (b >= 0 && r < il) ? 16u : 0u;
        int bs = b < 0 ? 0 : b;
        srcA[q] = (const char*)(g_A + ((size_t)bs * AROWS + r) * DDIM) + cc * 16;
        dstA[q] = sbase + row * PITCH + cc * 16;
    }
    const char* srcB[5]; uint32_t dstB[5], szB[5];
#pragma unroll
    for (int q = 0; q < 5; q++) {
        int idx = tid + q * 512, row = idx >> 3, cc = idx & 7;
        int blk = row >> 3;
        int j = g_bJ[jb * 40 + blk];
        int w = g_bW[jb * 40 + blk] + (row & 7);
        int sl = (j >= 0) ? (__ldg(&s_len[j]) - 3) : 0;
        szB[q] = (j >= 0 && w < sl) ? 16u : 0u;
        int js = j < 0 ? 0 : j;
        srcB[q] = (const char*)(g_S + ((size_t)js * SROWS + w) * DDIM) + cc * 16;
        dstB[q] = sbase + ASTAGE + row * PITCH + cc * 16;
    }

    // ldmatrix lane addresses
    const int quad = lane >> 3, r8 = lane & 7;
    const uint32_t a_lane = (uint32_t)((wm * 32 + (quad & 1) * 8 + r8) * PITCH
                                       + (quad >> 1) * 16);
    const uint32_t b_lane = (uint32_t)(ASTAGE
                                       + (wn * 80 + (quad >> 1) * 8 + r8) * PITCH
                                       + (quad & 1) * 16);

    float c[2][10][4];
#pragma unroll
    for (int mt = 0; mt < 2; mt++)
#pragma unroll
        for (int nt = 0; nt < 10; nt++)
#pragma unroll
            for (int q = 0; q < 4; q++) c[mt][nt][q] = 0.0f;

    // ---- prologue: 3 stages in flight ----
#pragma unroll
    for (int p = 0; p < 3; p++) {
        uint32_t so = (uint32_t)(p * STAGE_SZ), ko = (uint32_t)(p * 128);
#pragma unroll
        for (int q = 0; q < 2; q++) CP_ASYNC16Z(dstA[q] + so, srcA[q] + ko, szA[q]);
#pragma unroll
        for (int q = 0; q < 5; q++) CP_ASYNC16Z(dstB[q] + so, srcB[q] + ko, szB[q]);
        CP_COMMIT();
    }

    int stg = 0;
#pragma unroll 1
    for (int kt = 0; kt < 16; kt++) {
        CP_WAIT2();
        __syncthreads();

        const uint32_t stga = sbase + stg * STAGE_SZ;
#pragma unroll
        for (int step = 0; step < 4; step++) {
            uint32_t areg[2][4], breg[5][4];
#pragma unroll
            for (int mt = 0; mt < 2; mt++)
                LDSM4(areg[mt], stga + a_lane + mt * 16 * PITCH + step * 32);
#pragma unroll
            for (int nn = 0; nn < 5; nn++)
                LDSM4(breg[nn], stga + b_lane + nn * 16 * PITCH + step * 32);
#pragma unroll
            for (int mt = 0; mt < 2; mt++)
#pragma unroll
                for (int nt = 0; nt < 10; nt++)
                    MMA16816(c[mt][nt], areg[mt], breg[nt >> 1][(nt & 1) * 2],
                             breg[nt >> 1][(nt & 1) * 2 + 1]);
        }
        __syncthreads();
        if (kt + 3 < 16) {
            uint32_t so = (uint32_t)(stg * STAGE_SZ), ko = (uint32_t)((kt + 3) * 128);
#pragma unroll
            for (int q = 0; q < 2; q++) CP_ASYNC16Z(dstA[q] + so, srcA[q] + ko, szA[q]);
#pragma unroll
            for (int q = 0; q < 5; q++) CP_ASYNC16Z(dstB[q] + so, srcB[q] + ko, szB[q]);
        }
        CP_COMMIT();
        stg = (stg + 1 == 3) ? 0 : stg + 1;
    }
    __syncthreads();       // compute done; smem reused for C

    // ---- store C tile to smem: [128][CPITCH] floats ----
    float* C  = (float*)smem;
    float* RM = (float*)(smem + 128 * CPITCH * 4);   // [128][40] row maxes
    float* CM = RM + 128 * 40;                       // [8][320] col maxes
#pragma unroll
    for (int mt = 0; mt < 2; mt++)
#pragma unroll
        for (int nt = 0; nt < 10; nt++) {
            int row = wm * 32 + mt * 16 + (lane >> 2);
            int col = wn * 80 + nt * 8 + (lane & 3) * 2;
            *(float2*)&C[row * CPITCH + col]       = make_float2(c[mt][nt][0], c[mt][nt][1]);
            *(float2*)&C[(row + 8) * CPITCH + col] = make_float2(c[mt][nt][2], c[mt][nt][3]);
        }
    __syncthreads();

    const int nmb = g_mN[ib], njb = g_nN[jb];

    // ---- row part: per row, per j-batch: max over w<sl (+0 iff sl<37) ----
    if (tid < 128) {
        const float* Cr = &C[tid * CPITCH];
        for (int js = 0; js < njb; js++) {
            int cs = g_nCS[jb * 40 + js], sl = g_nSL[jb * 40 + js];
            float m = Cr[cs];
            for (int w = 1; w < sl; w++) m = fmaxf(m, Cr[cs + w]);
            if (sl < 37) m = fmaxf(m, 0.0f);
            RM[tid * 40 + js] = m;
        }
    }
    // ---- col part: per col, per m-batch: max over r<il (+0 iff il<49) ----
    if (tid < 320) {
        for (int ms = 0; ms < nmb; ms++) {
            int rs = g_mRS[ib * 8 + ms], il = g_mIL[ib * 8 + ms];
            float m = C[rs * CPITCH + tid];
            for (int r = 1; r < il; r++) m = fmaxf(m, C[(rs + r) * CPITCH + tid]);
            if (il < 49) m = fmaxf(m, 0.0f);
            CM[ms * 320 + tid] = m;
        }
    }
    __syncthreads();

    // ---- per-pair reduction & output ----
    if (tid < nmb * njb) {
        int ms = tid / njb, js = tid - ms * njb;
        int rs = g_mRS[ib * 8 + ms], il = g_mIL[ib * 8 + ms];
        int cs = g_nCS[jb * 40 + js], sl = g_nSL[jb * 40 + js];
        float sum = 0.0f;
        for (int r = 0; r < il; r++) sum += RM[(rs + r) * 40 + js];
        for (int w = 0; w < sl; w++) sum += CM[ms * 320 + cs + w];
        out[g_mB[ib * 8 + ms] * NBATCH + g_nB[jb * 40 + js]] = sum;
    }
}

extern "C" void kernel_launch(void* const* d_in, const int* in_sizes, int n_in,
                              void* d_out, int out_size) {
    (void)in_sizes; (void)n_in; (void)out_size;
    const float* im   = (const float*)d_in[0];
    const float* s    = (const float*)d_in[1];
    const int* im_len = (const int*)d_in[2];
    const int* s_len  = (const int*)d_in[3];
    float* out = (float*)d_out;

    plan_kernel<<<1, 32>>>(im_len, s_len);
    convA_kernel<<<4096, 256>>>(im, im_len);
    convS_kernel<<<2560, 256>>>(s, s_len);

    cudaFuncSetAttribute(align_gemm_kernel,
                         cudaFuncAttributeMaxDynamicSharedMemorySize, SMEM_BYTES);
    dim3 grid(16, 64);
    align_gemm_kernel<<<grid, 512, SMEM_BYTES>>>(im_len, s_len, out);
}

// round 10
// speedup vs baseline: 1.5995x; 1.0668x over previous
#include <cuda_runtime.h>
#include <cuda_fp16.h>
#include <cstdint>

// Problem: B=128, L_IM=50, L_S=40, D=1024
// im = im_set[:,1:,:]  -> il = im_len-1 valid rows (9..49)
// s  = s_seq[:,1:-2,:] -> sl = s_len-3  valid rows (7..37)
// Batches are bin-packed (whole) into dense GEMM tiles:
//   M: ceil(il/16) x 16-row fragments, 8 per 128-row tile  (<= 64 tiles)
//   N: ceil(sl/8)  x 8-col blocks,   40 per 320-col tile  (<= 16 tiles)
// Mainloop is fully dense (no masks). Pad rows/cols inside rounded
// fragments are exact zeros via cp.async zfill.
#define NBATCH 128
#define DDIM   1024
#define AROWS  64
#define SROWS  40

__device__ __align__(1024) __half g_A[(size_t)NBATCH * AROWS * DDIM];  // 16 MB
__device__ __align__(1024) __half g_S[(size_t)NBATCH * SROWS * DDIM];  // 10 MB

// ---- packing plan ----
__device__ int g_TM, g_TN;
__device__ int g_fB[64 * 8],  g_fR[64 * 8];    // M tile fragment -> batch, row base
__device__ int g_mN[64], g_mB[64 * 8], g_mRS[64 * 8], g_mIL[64 * 8];
__device__ int g_bJ[16 * 40], g_bW[16 * 40];   // N tile block -> batch, w base
__device__ int g_nN[16], g_nB[16 * 40], g_nCS[16 * 40], g_nSL[16 * 40];

// ---------------- helpers ----------------
__device__ __forceinline__ uint32_t smem_u32(const void* p) {
    uint32_t a;
    asm("{ .reg .u64 t; cvta.to.shared.u64 t, %1; cvt.u32.u64 %0, t; }" : "=r"(a) : "l"(p));
    return a;
}

#define CP_ASYNC16Z(dst, src, sz) \
    asm volatile("cp.async.cg.shared.global [%0], [%1], 16, %2;" \
                 :: "r"(dst), "l"(src), "r"(sz))
#define CP_COMMIT() asm volatile("cp.async.commit_group;" ::: "memory")
#define CP_WAIT2()  asm volatile("cp.async.wait_group 2;" ::: "memory")

#define LDSM4(r, addr) \
    asm volatile("ldmatrix.sync.aligned.m8n8.x4.shared.b16 {%0,%1,%2,%3}, [%4];" \
                 : "=r"((r)[0]), "=r"((r)[1]), "=r"((r)[2]), "=r"((r)[3]) : "r"(addr))

#define MMA16816(c, a, b0, b1) \
    asm volatile("mma.sync.aligned.m16n8k16.row.col.f32.f16.f16.f32 " \
                 "{%0,%1,%2,%3},{%4,%5,%6,%7},{%8,%9},{%0,%1,%2,%3};" \
                 : "+f"((c)[0]), "+f"((c)[1]), "+f"((c)[2]), "+f"((c)[3]) \
                 : "r"((a)[0]), "r"((a)[1]), "r"((a)[2]), "r"((a)[3]), "r"(b0), "r"(b1))

// ------------- planner: bin-pack batches into tiles (smem-staged) -------------
__global__ void plan_kernel(const int* __restrict__ im_len, const int* __restrict__ s_len) {
    __shared__ int il[NBATCH], sl[NBATCH];
    __shared__ int s_fB[64 * 8], s_fR[64 * 8];
    __shared__ int s_mN[64], s_mB[64 * 8], s_mRS[64 * 8], s_mIL[64 * 8];
    __shared__ int s_bJ[16 * 40], s_bW[16 * 40];
    __shared__ int s_nN[16], s_nB[16 * 40], s_nCS[16 * 40], s_nSL[16 * 40];
    __shared__ int s_TM, s_TN;
    const int t = threadIdx.x;

    if (t < NBATCH) {
        int v = im_len[t] - 1;  il[t] = v < 1 ? 1 : (v > 49 ? 49 : v);
        int w = s_len[t] - 3;   sl[t] = w < 1 ? 1 : (w > 37 ? 37 : w);
    }
    for (int k = t; k < 64 * 8; k += 128)  { s_fB[k] = -1; s_fR[k] = 0; s_mB[k] = 0; s_mRS[k] = 0; s_mIL[k] = 1; }
    for (int k = t; k < 16 * 40; k += 128) { s_bJ[k] = -1; s_bW[k] = 0; s_nB[k] = 0; s_nCS[k] = 0; s_nSL[k] = 1; }
    for (int k = t; k < 64; k += 128) s_mN[k] = 0;
    if (t < 16) s_nN[t] = 0;
    __syncthreads();

    if (t == 0) {
        // ---- M side ----
        int tm = 0, used = 0;
        for (int f = 4; f >= 1; f--) {
#pragma unroll 8
            for (int i = 0; i < NBATCH; i++) {
                int v = il[i];
                int fr = (v + 15) >> 4;
                if (fr != f) continue;
                if (used + fr > 8) { tm++; used = 0; }
                int slot = s_mN[tm]++;
                s_mB[tm * 8 + slot]  = i;
                s_mRS[tm * 8 + slot] = used * 16;
                s_mIL[tm * 8 + slot] = v;
                for (int k = 0; k < fr; k++) {
                    s_fB[tm * 8 + used + k] = i;
                    s_fR[tm * 8 + used + k] = k * 16;
                }
                used += fr;
            }
        }
        s_TM = tm + (used > 0 ? 1 : 0);
        // ---- N side ----
        int tn = 0; used = 0;
        for (int f = 5; f >= 1; f--) {
#pragma unroll 8
            for (int j = 0; j < NBATCH; j++) {
                int v = sl[j];
                int bl = (v + 7) >> 3;
                if (bl != f) continue;
                if (used + bl > 40) { tn++; used = 0; }
                int slot = s_nN[tn]++;
                s_nB[tn * 40 + slot]  = j;
                s_nCS[tn * 40 + slot] = used * 8;
                s_nSL[tn * 40 + slot] = v;
                for (int k = 0; k < bl; k++) {
                    s_bJ[tn * 40 + used + k] = j;
                    s_bW[tn * 40 + used + k] = k * 8;
                }
                used += bl;
            }
        }
        s_TN = tn + (used > 0 ? 1 : 0);
    }
    __syncthreads();

    // ---- coalesced copy-out ----
    for (int k = t; k < 64 * 8; k += 128) {
        g_fB[k] = s_fB[k];  g_fR[k] = s_fR[k];
        g_mB[k] = s_mB[k];  g_mRS[k] = s_mRS[k];  g_mIL[k] = s_mIL[k];
    }
    for (int k = t; k < 16 * 40; k += 128) {
        g_bJ[k] = s_bJ[k];  g_bW[k] = s_bW[k];
        g_nB[k] = s_nB[k];  g_nCS[k] = s_nCS[k];  g_nSL[k] = s_nSL[k];
    }
    for (int k = t; k < 64; k += 128) g_mN[k] = s_mN[k];
    if (t < 16) g_nN[t] = s_nN[t];
    if (t == 0) { g_TM = s_TM; g_TN = s_TN; }
}

// ------------- conversion: fp32 -> fp16, valid rows only -------------
__global__ void convA_kernel(const float* __restrict__ im, const int* __restrict__ im_len) {
    int u = blockIdx.x * blockDim.x + threadIdx.x;        // < 128*64*128
    int i  = u >> 13;
    int r  = (u >> 7) & 63;
    int d0 = (u & 127) << 3;
    int L = im_len[i] - 1;
    if (r >= L || r >= 49) return;                        // rows never read (zfill)
    const float* src = im + ((size_t)i * 50 + r + 1) * DDIM + d0;
    float4 f0 = ((const float4*)src)[0];
    float4 f1 = ((const float4*)src)[1];
    union { uint4 v; __half2 h[4]; } pk;
    pk.h[0] = __float22half2_rn(make_float2(f0.x, f0.y));
    pk.h[1] = __float22half2_rn(make_float2(f0.z, f0.w));
    pk.h[2] = __float22half2_rn(make_float2(f1.x, f1.y));
    pk.h[3] = __float22half2_rn(make_float2(f1.z, f1.w));
    *((uint4*)(g_A + ((size_t)i * AROWS + r) * DDIM + d0)) = pk.v;
}

__global__ void convS_kernel(const float* __restrict__ s, const int* __restrict__ s_len) {
    int u = blockIdx.x * blockDim.x + threadIdx.x;        // < 128*40*128
    int i   = u / (SROWS * 128);
    int rem = u - i * (SROWS * 128);
    int r  = rem >> 7;
    int d0 = (rem & 127) << 3;
    int L = s_len[i] - 3;
    if (r >= L || r >= 37) return;
    const float* src = s + ((size_t)i * 40 + r + 1) * DDIM + d0;
    float4 f0 = ((const float4*)src)[0];
    float4 f1 = ((const float4*)src)[1];
    union { uint4 v; __half2 h[4]; } pk;
    pk.h[0] = __float22half2_rn(make_float2(f0.x, f0.y));
    pk.h[1] = __float22half2_rn(make_float2(f0.z, f0.w));
    pk.h[2] = __float22half2_rn(make_float2(f1.x, f1.y));
    pk.h[3] = __float22half2_rn(make_float2(f1.z, f1.w));
    *((uint4*)(g_S + ((size_t)i * SROWS + r) * DDIM + d0)) = pk.v;
}

// ------------- dense packed GEMM + per-pair masked max/sum epilogue -------------
// CTA: 512 threads, tile M=128 x N=320, K=1024 in 16 chunks of 64.
// Warp grid 4(m) x 4(n): warp tile 32 x 80 (the proven R6 mainloop, unmodified).
#define PITCH     144
#define ASTAGE    18432              // 128*144
#define STAGE_SZ  64512              // ASTAGE + 320*144
#define CPITCH    326                // even -> float2-aligned; 326*4 % 128 = 24
// epilogue: C (128*CPITCH) + RM (128*40) + CM (8*320) = 197632 B  (> mainloop 193664)
#define SMEM_BYTES 197632

__global__ void __launch_bounds__(512, 1) align_gemm_kernel(
        const int* __restrict__ im_len, const int* __restrict__ s_len,
        float* __restrict__ out) {
    const int jb = blockIdx.x;       // N tile
    const int ib = blockIdx.y;       // M tile
    if (ib >= g_TM || jb >= g_TN) return;

    extern __shared__ __align__(16) char smem[];
    const int tid  = threadIdx.x;
    const int lane = tid & 31;
    const int wid  = tid >> 5;
    const int wm   = wid & 3;        // M offset wm*32
    const int wn   = wid >> 2;       // N offset wn*80
    const uint32_t sbase = smem_u32(smem) + 128;

    // ---- per-thread load setup (advance src by 128B per kt) ----
    const char* srcA[2]; uint32_t dstA[2], szA[2];
#pragma unroll
    for (int q = 0; q < 2; q++) {
        int idx = tid + q * 512, row = idx >> 3, cc = idx & 7;
        int f = row >> 4;
        int b = g_fB[ib * 8 + f];
        int r = g_fR[ib * 8 + f] + (row & 15);
        int il = (b >= 0) ? (__ldg(&im_len[b]) - 1) : 0;
        szA[q] = (b >= 0 && r < il) ? 16u : 0u;
        int bs = b < 0 ? 0 : b;
        srcA[q] = (const char*)(g_A + ((size_t)bs * AROWS + r) * DDIM) + cc * 16;
        dstA[q] = sbase + row * PITCH + cc * 16;
    }
    const char* srcB[5]; uint32_t dstB[5], szB[5];
#pragma unroll
    for (int q = 0; q < 5; q++) {
        int idx = tid + q * 512, row = idx >> 3, cc = idx & 7;
        int blk = row >> 3;
        int j = g_bJ[jb * 40 + blk];
        int w = g_bW[jb * 40 + blk] + (row & 7);
        int sl = (j >= 0) ? (__ldg(&s_len[j]) - 3) : 0;
        szB[q] = (j >= 0 && w < sl) ? 16u : 0u;
        int js = j < 0 ? 0 : j;
        srcB[q] = (const char*)(g_S + ((size_t)js * SROWS + w) * DDIM) + cc * 16;
        dstB[q] = sbase + ASTAGE + row * PITCH + cc * 16;
    }

    // ldmatrix lane addresses
    const int quad = lane >> 3, r8 = lane & 7;
    const uint32_t a_lane = (uint32_t)((wm * 32 + (quad & 1) * 8 + r8) * PITCH
                                       + (quad >> 1) * 16);
    const uint32_t b_lane = (uint32_t)(ASTAGE
                                       + (wn * 80 + (quad >> 1) * 8 + r8) * PITCH
                                       + (quad & 1) * 16);

    float c[2][10][4];
#pragma unroll
    for (int mt = 0; mt < 2; mt++)
#pragma unroll
        for (int nt = 0; nt < 10; nt++)
#pragma unroll
            for (int q = 0; q < 4; q++) c[mt][nt][q] = 0.0f;

    // ---- prologue: 3 stages in flight ----
#pragma unroll
    for (int p = 0; p < 3; p++) {
        uint32_t so = (uint32_t)(p * STAGE_SZ), ko = (uint32_t)(p * 128);
#pragma unroll
        for (int q = 0; q < 2; q++) CP_ASYNC16Z(dstA[q] + so, srcA[q] + ko, szA[q]);
#pragma unroll
        for (int q = 0; q < 5; q++) CP_ASYNC16Z(dstB[q] + so, srcB[q] + ko, szB[q]);
        CP_COMMIT();
    }

    int stg = 0;
#pragma unroll 1
    for (int kt = 0; kt < 16; kt++) {
        CP_WAIT2();
        __syncthreads();

        const uint32_t stga = sbase + stg * STAGE_SZ;
#pragma unroll
        for (int step = 0; step < 4; step++) {
            uint32_t areg[2][4], breg[5][4];
#pragma unroll
            for (int mt = 0; mt < 2; mt++)
                LDSM4(areg[mt], stga + a_lane + mt * 16 * PITCH + step * 32);
#pragma unroll
            for (int nn = 0; nn < 5; nn++)
                LDSM4(breg[nn], stga + b_lane + nn * 16 * PITCH + step * 32);
#pragma unroll
            for (int mt = 0; mt < 2; mt++)
#pragma unroll
                for (int nt = 0; nt < 10; nt++)
                    MMA16816(c[mt][nt], areg[mt], breg[nt >> 1][(nt & 1) * 2],
                             breg[nt >> 1][(nt & 1) * 2 + 1]);
        }
        __syncthreads();
        if (kt + 3 < 16) {
            uint32_t so = (uint32_t)(stg * STAGE_SZ), ko = (uint32_t)((kt + 3) * 128);
#pragma unroll
            for (int q = 0; q < 2; q++) CP_ASYNC16Z(dstA[q] + so, srcA[q] + ko, szA[q]);
#pragma unroll
            for (int q = 0; q < 5; q++) CP_ASYNC16Z(dstB[q] + so, srcB[q] + ko, szB[q]);
        }
        CP_COMMIT();
        stg = (stg + 1 == 3) ? 0 : stg + 1;
    }
    __syncthreads();       // compute done; smem reused for C

    // ---- store C tile to smem: [128][CPITCH] floats ----
    float* C  = (float*)smem;
    float* RM = (float*)(smem + 128 * CPITCH * 4);   // [128][40] row maxes
    float* CM = RM + 128 * 40;                       // [8][320] col maxes
#pragma unroll
    for (int mt = 0; mt < 2; mt++)
#pragma unroll
        for (int nt = 0; nt < 10; nt++) {
            int row = wm * 32 + mt * 16 + (lane >> 2);
            int col = wn * 80 + nt * 8 + (lane & 3) * 2;
            *(float2*)&C[row * CPITCH + col]       = make_float2(c[mt][nt][0], c[mt][nt][1]);
            *(float2*)&C[(row + 8) * CPITCH + col] = make_float2(c[mt][nt][2], c[mt][nt][3]);
        }
    __syncthreads();

    const int nmb = g_mN[ib], njb = g_nN[jb];

    // ---- row part: per row, per j-batch: max over w<sl (+0 iff sl<37) ----
    if (tid < 128) {
        const float* Cr = &C[tid * CPITCH];
        for (int js = 0; js < njb; js++) {
            int cs = g_nCS[jb * 40 + js], sl = g_nSL[jb * 40 + js];
            float m = Cr[cs];
            for (int w = 1; w < sl; w++) m = fmaxf(m, Cr[cs + w]);
            if (sl < 37) m = fmaxf(m, 0.0f);
            RM[tid * 40 + js] = m;
        }
    }
    // ---- col part: per col, per m-batch: max over r<il (+0 iff il<49) ----
    if (tid < 320) {
        for (int ms = 0; ms < nmb; ms++) {
            int rs = g_mRS[ib * 8 + ms], il = g_mIL[ib * 8 + ms];
            float m = C[rs * CPITCH + tid];
            for (int r = 1; r < il; r++) m = fmaxf(m, C[(rs + r) * CPITCH + tid]);
            if (il < 49) m = fmaxf(m, 0.0f);
            CM[ms * 320 + tid] = m;
        }
    }
    __syncthreads();

    // ---- per-pair reduction & output ----
    if (tid < nmb * njb) {
        int ms = tid / njb, js = tid - ms * njb;
        int rs = g_mRS[ib * 8 + ms], il = g_mIL[ib * 8 + ms];
        int cs = g_nCS[jb * 40 + js], sl = g_nSL[jb * 40 + js];
        float sum = 0.0f;
        for (int r = 0; r < il; r++) sum += RM[(rs + r) * 40 + js];
        for (int w = 0; w < sl; w++) sum += CM[ms * 320 + cs + w];
        out[g_mB[ib * 8 + ms] * NBATCH + g_nB[jb * 40 + js]] = sum;
    }
}

extern "C" void kernel_launch(void* const* d_in, const int* in_sizes, int n_in,
                              void* d_out, int out_size) {
    (void)in_sizes; (void)n_in; (void)out_size;
    const float* im   = (const float*)d_in[0];
    const float* s    = (const float*)d_in[1];
    const int* im_len = (const int*)d_in[2];
    const int* s_len  = (const int*)d_in[3];
    float* out = (float*)d_out;

    plan_kernel<<<1, 128>>>(im_len, s_len);
    convA_kernel<<<4096, 256>>>(im, im_len);
    convS_kernel<<<2560, 256>>>(s, s_len);

    cudaFuncSetAttribute(align_gemm_kernel,
                         cudaFuncAttributeMaxDynamicSharedMemorySize, SMEM_BYTES);
    dim3 grid(16, 64);
    align_gemm_kernel<<<grid, 512, SMEM_BYTES>>>(im_len, s_len, out);
}

// round 11
// speedup vs baseline: 1.8703x; 1.1693x over previous
#include <cuda_runtime.h>
#include <cuda_fp16.h>
#include <cstdint>

// Problem: B=128, L_IM=50, L_S=40, D=1024
// im = im_set[:,1:,:]  -> il = im_len-1 valid rows (9..49)
// s  = s_seq[:,1:-2,:] -> sl = s_len-3  valid rows (7..37)
// Batches are bin-packed (whole) into dense GEMM tiles:
//   M: ceil(il/16) x 16-row fragments, 8 per 128-row tile  (<= 64 tiles)
//   N: ceil(sl/8)  x 8-col blocks,   40 per 320-col tile  (<= 16 tiles)
// Mainloop fully dense; pad rows/cols inside fragments are exact zeros (zfill).
#define NBATCH 128
#define DDIM   1024
#define AROWS  64
#define SROWS  40

__device__ __align__(1024) __half g_A[(size_t)NBATCH * AROWS * DDIM];  // 16 MB
__device__ __align__(1024) __half g_S[(size_t)NBATCH * SROWS * DDIM];  // 10 MB

// ---- packing plan ----
__device__ int g_TM, g_TN;
__device__ int g_fB[64 * 8],  g_fR[64 * 8];    // M tile fragment -> batch, row base
__device__ int g_mN[64], g_mB[64 * 8], g_mRS[64 * 8], g_mIL[64 * 8];
__device__ int g_bJ[16 * 40], g_bW[16 * 40];   // N tile block -> batch, w base
__device__ int g_nN[16], g_nB[16 * 40], g_nCS[16 * 40], g_nSL[16 * 40];

// ---------------- helpers ----------------
__device__ __forceinline__ uint32_t smem_u32(const void* p) {
    uint32_t a;
    asm("{ .reg .u64 t; cvta.to.shared.u64 t, %1; cvt.u32.u64 %0, t; }" : "=r"(a) : "l"(p));
    return a;
}

#define CP_ASYNC16Z(dst, src, sz) \
    asm volatile("cp.async.cg.shared.global [%0], [%1], 16, %2;" \
                 :: "r"(dst), "l"(src), "r"(sz))
#define CP_COMMIT() asm volatile("cp.async.commit_group;" ::: "memory")
#define CP_WAIT1()  asm volatile("cp.async.wait_group 1;" ::: "memory")

#define LDSM4(r, addr) \
    asm volatile("ldmatrix.sync.aligned.m8n8.x4.shared.b16 {%0,%1,%2,%3}, [%4];" \
                 : "=r"((r)[0]), "=r"((r)[1]), "=r"((r)[2]), "=r"((r)[3]) : "r"(addr))

#define MMA16816(c, a, b0, b1) \
    asm volatile("mma.sync.aligned.m16n8k16.row.col.f32.f16.f16.f32 " \
                 "{%0,%1,%2,%3},{%4,%5,%6,%7},{%8,%9},{%0,%1,%2,%3};" \
                 : "+f"((c)[0]), "+f"((c)[1]), "+f"((c)[2]), "+f"((c)[3]) \
                 : "r"((a)[0]), "r"((a)[1]), "r"((a)[2]), "r"((a)[3]), "r"(b0), "r"(b1))

// ------------- planner: parallel class-rank + short serial walk -------------
__global__ void plan_kernel(const int* __restrict__ im_len, const int* __restrict__ s_len) {
    __shared__ int il[NBATCH], sl[NBATCH];
    __shared__ int ordM[NBATCH], ordN[NBATCH];
    __shared__ int wcM[4][5], wcN[4][6];           // [warp][class]
    __shared__ int s_fB[64 * 8], s_fR[64 * 8];
    __shared__ int s_mN[64], s_mB[64 * 8], s_mRS[64 * 8], s_mIL[64 * 8];
    __shared__ int s_bJ[16 * 40], s_bW[16 * 40];
    __shared__ int s_nN[16], s_nB[16 * 40], s_nCS[16 * 40], s_nSL[16 * 40];
    __shared__ int s_TM, s_TN;
    const int t = threadIdx.x, w = t >> 5, ln = t & 31;
    const uint32_t lmask = (1u << ln) - 1u;

    int vI = im_len[t] - 1;  vI = vI < 1 ? 1 : (vI > 49 ? 49 : vI);  il[t] = vI;
    int vS = s_len[t] - 3;   vS = vS < 1 ? 1 : (vS > 37 ? 37 : vS);  sl[t] = vS;
    const int frM = (vI + 15) >> 4;   // 1..4
    const int frN = (vS + 7) >> 3;    // 1..5

    int rkM = 0, rkN = 0;
#pragma unroll
    for (int c = 1; c <= 4; c++) {
        uint32_t b = __ballot_sync(0xffffffffu, frM == c);
        if (frM == c) rkM = __popc(b & lmask);
        if (ln == 0) wcM[w][c] = __popc(b);
    }
#pragma unroll
    for (int c = 1; c <= 5; c++) {
        uint32_t b = __ballot_sync(0xffffffffu, frN == c);
        if (frN == c) rkN = __popc(b & lmask);
        if (ln == 0) wcN[w][c] = __popc(b);
    }
    for (int k = t; k < 64 * 8; k += 128)  { s_fB[k] = -1; s_fR[k] = 0; s_mB[k] = 0; s_mRS[k] = 0; s_mIL[k] = 1; }
    for (int k = t; k < 16 * 40; k += 128) { s_bJ[k] = -1; s_bW[k] = 0; s_nB[k] = 0; s_nCS[k] = 0; s_nSL[k] = 1; }
    if (t < 64) s_mN[t] = 0;
    if (t < 16) s_nN[t] = 0;
    __syncthreads();

    // ordered position: classes DESCENDING, index ascending within class
    {
        int base = 0;
#pragma unroll
        for (int c = 4; c > 0; c--) {
            if (c > frM) base += wcM[0][c] + wcM[1][c] + wcM[2][c] + wcM[3][c];
        }
        for (int ww = 0; ww < 4; ww++) if (ww < w) base += wcM[ww][frM];
        ordM[base + rkM] = t;
    }
    {
        int base = 0;
#pragma unroll
        for (int c = 5; c > 0; c--) {
            if (c > frN) base += wcN[0][c] + wcN[1][c] + wcN[2][c] + wcN[3][c];
        }
        for (int ww = 0; ww < 4; ww++) if (ww < w) base += wcN[ww][frN];
        ordN[base + rkN] = t;
    }
    __syncthreads();

    if (t == 0) {                       // M walk (128 iters)
        int tm = 0, used = 0;
        for (int k = 0; k < NBATCH; k++) {
            int i = ordM[k], v = il[i], fr = (v + 15) >> 4;
            if (used + fr > 8) { tm++; used = 0; }
            int slot = s_mN[tm]++;
            s_mB[tm * 8 + slot]  = i;
            s_mRS[tm * 8 + slot] = used * 16;
            s_mIL[tm * 8 + slot] = v;
            for (int q = 0; q < fr; q++) {
                s_fB[tm * 8 + used + q] = i;
                s_fR[tm * 8 + used + q] = q * 16;
            }
            used += fr;
        }
        s_TM = tm + (used > 0 ? 1 : 0);
    }
    if (t == 1) {                       // N walk (parallel with M walk)
        int tn = 0, used = 0;
        for (int k = 0; k < NBATCH; k++) {
            int j = ordN[k], v = sl[j], bl = (v + 7) >> 3;
            if (used + bl > 40) { tn++; used = 0; }
            int slot = s_nN[tn]++;
            s_nB[tn * 40 + slot]  = j;
            s_nCS[tn * 40 + slot] = used * 8;
            s_nSL[tn * 40 + slot] = v;
            for (int q = 0; q < bl; q++) {
                s_bJ[tn * 40 + used + q] = j;
                s_bW[tn * 40 + used + q] = q * 8;
            }
            used += bl;
        }
        s_TN = tn + (used > 0 ? 1 : 0);
    }
    __syncthreads();

    for (int k = t; k < 64 * 8; k += 128) {
        g_fB[k] = s_fB[k];  g_fR[k] = s_fR[k];
        g_mB[k] = s_mB[k];  g_mRS[k] = s_mRS[k];  g_mIL[k] = s_mIL[k];
    }
    for (int k = t; k < 16 * 40; k += 128) {
        g_bJ[k] = s_bJ[k];  g_bW[k] = s_bW[k];
        g_nB[k] = s_nB[k];  g_nCS[k] = s_nCS[k];  g_nSL[k] = s_nSL[k];
    }
    if (t < 64) g_mN[t] = s_mN[t];
    if (t < 16) g_nN[t] = s_nN[t];
    if (t == 0) { g_TM = s_TM; g_TN = s_TN; }
}

// ------------- merged conversion: fp32 -> fp16, valid rows only -------------
__global__ void conv_kernel(const float* __restrict__ im, const float* __restrict__ s,
                            const int* __restrict__ im_len, const int* __restrict__ s_len) {
    int b = blockIdx.x;
    if (b < 4096) {                                     // A path
        int u = b * 256 + threadIdx.x;                  // < 128*64*128
        int i  = u >> 13;
        int r  = (u >> 7) & 63;
        int d0 = (u & 127) << 3;
        int L = im_len[i] - 1;
        if (r >= L || r >= 49) return;
        const float* src = im + ((size_t)i * 50 + r + 1) * DDIM + d0;
        float4 f0 = ((const float4*)src)[0];
        float4 f1 = ((const float4*)src)[1];
        union { uint4 v; __half2 h[4]; } pk;
        pk.h[0] = __float22half2_rn(make_float2(f0.x, f0.y));
        pk.h[1] = __float22half2_rn(make_float2(f0.z, f0.w));
        pk.h[2] = __float22half2_rn(make_float2(f1.x, f1.y));
        pk.h[3] = __float22half2_rn(make_float2(f1.z, f1.w));
        *((uint4*)(g_A + ((size_t)i * AROWS + r) * DDIM + d0)) = pk.v;
    } else {                                            // S path
        int u = (b - 4096) * 256 + threadIdx.x;         // < 128*40*128
        int i   = u / (SROWS * 128);
        int rem = u - i * (SROWS * 128);
        int r  = rem >> 7;
        int d0 = (rem & 127) << 3;
        int L = s_len[i] - 3;
        if (r >= L || r >= 37) return;
        const float* src = s + ((size_t)i * 40 + r + 1) * DDIM + d0;
        float4 f0 = ((const float4*)src)[0];
        float4 f1 = ((const float4*)src)[1];
        union { uint4 v; __half2 h[4]; } pk;
        pk.h[0] = __float22half2_rn(make_float2(f0.x, f0.y));
        pk.h[1] = __float22half2_rn(make_float2(f0.z, f0.w));
        pk.h[2] = __float22half2_rn(make_float2(f1.x, f1.y));
        pk.h[3] = __float22half2_rn(make_float2(f1.z, f1.w));
        *((uint4*)(g_S + ((size_t)i * SROWS + r) * DDIM + d0)) = pk.v;
    }
}

// ------------- dense packed GEMM + per-pair masked max/sum epilogue -------------
// CTA: 512 threads, tile M=128 x N=320, K=1024 in 16 chunks of 64.
// Warp grid 4(m) x 4(n): warp tile 32 x 80. ONE barrier per k-chunk.
#define PITCH     144
#define ASTAGE    18432              // 128*144
#define STAGE_SZ  64512              // ASTAGE + 320*144
#define CPITCH    326                // even -> float2-aligned; 326*4 % 128 = 24
#define SMEM_BYTES 197632            // C (128*CPITCH*4) + RM (128*40*4) + CM (8*320*4)

__global__ void __launch_bounds__(512, 1) align_gemm_kernel(
        const int* __restrict__ im_len, const int* __restrict__ s_len,
        float* __restrict__ out) {
    const int jb = blockIdx.x;       // N tile
    const int ib = blockIdx.y;       // M tile
    if (ib >= g_TM || jb >= g_TN) return;

    extern __shared__ __align__(16) char smem[];
    const int tid  = threadIdx.x;
    const int lane = tid & 31;
    const int wid  = tid >> 5;
    const int wm   = wid & 3;        // M offset wm*32
    const int wn   = wid >> 2;       // N offset wn*80
    const uint32_t sbase = smem_u32(smem) + 128;

    // ---- per-thread load setup (advance src by 128B per kt) ----
    const char* srcA[2]; uint32_t dstA[2], szA[2];
#pragma unroll
    for (int q = 0; q < 2; q++) {
        int idx = tid + q * 512, row = idx >> 3, cc = idx & 7;
        int f = row >> 4;
        int b = g_fB[ib * 8 + f];
        int r = g_fR[ib * 8 + f] + (row & 15);
        int il = (b >= 0) ? (__ldg(&im_len[b]) - 1) : 0;
        szA[q] = (b >= 0 && r < il) ? 16u : 0u;
        int bs = b < 0 ? 0 : b;
        srcA[q] = (const char*)(g_A + ((size_t)bs * AROWS + r) * DDIM) + cc * 16;
        dstA[q] = sbase + row * PITCH + cc * 16;
    }
    const char* srcB[5]; uint32_t dstB[5], szB[5];
#pragma unroll
    for (int q = 0; q < 5; q++) {
        int idx = tid + q * 512, row = idx >> 3, cc = idx & 7;
        int blk = row >> 3;
        int j = g_bJ[jb * 40 + blk];
        int w = g_bW[jb * 40 + blk] + (row & 7);
        int sl = (j >= 0) ? (__ldg(&s_len[j]) - 3) : 0;
        szB[q] = (j >= 0 && w < sl) ? 16u : 0u;
        int js = j < 0 ? 0 : j;
        srcB[q] = (const char*)(g_S + ((size_t)js * SROWS + w) * DDIM) + cc * 16;
        dstB[q] = sbase + ASTAGE + row * PITCH + cc * 16;
    }

    // ldmatrix lane addresses
    const int quad = lane >> 3, r8 = lane & 7;
    const uint32_t a_lane = (uint32_t)((wm * 32 + (quad & 1) * 8 + r8) * PITCH
                                       + (quad >> 1) * 16);
    const uint32_t b_lane = (uint32_t)(ASTAGE
                                       + (wn * 80 + (quad >> 1) * 8 + r8) * PITCH
                                       + (quad & 1) * 16);

    float c[2][10][4];
#pragma unroll
    for (int mt = 0; mt < 2; mt++)
#pragma unroll
        for (int nt = 0; nt < 10; nt++)
#pragma unroll
            for (int q = 0; q < 4; q++) c[mt][nt][q] = 0.0f;

    // ---- prologue: 2 stages in flight ----
#pragma unroll
    for (int p = 0; p < 2; p++) {
        uint32_t so = (uint32_t)(p * STAGE_SZ), ko = (uint32_t)(p * 128);
#pragma unroll
        for (int q = 0; q < 2; q++) CP_ASYNC16Z(dstA[q] + so, srcA[q] + ko, szA[q]);
#pragma unroll
        for (int q = 0; q < 5; q++) CP_ASYNC16Z(dstB[q] + so, srcB[q] + ko, szB[q]);
        CP_COMMIT();
    }

    int stg = 0, stg_load = 2;
#pragma unroll 1
    for (int kt = 0; kt < 16; kt++) {
        CP_WAIT1();            // loads for kt complete (only kt+1's group may pend)
        __syncthreads();       // data visible; stage (kt-1)%3 == (kt+2)%3 consumer-free

        if (kt + 2 < 16) {     // prefetch kt+2 BEFORE compute -> overlaps this kt
            uint32_t so = (uint32_t)(stg_load * STAGE_SZ), ko = (uint32_t)((kt + 2) * 128);
#pragma unroll
            for (int q = 0; q < 2; q++) CP_ASYNC16Z(dstA[q] + so, srcA[q] + ko, szA[q]);
#pragma unroll
            for (int q = 0; q < 5; q++) CP_ASYNC16Z(dstB[q] + so, srcB[q] + ko, szB[q]);
        }
        CP_COMMIT();           // empty commits at tail keep wait_group accounting
        stg_load = (stg_load + 1 == 3) ? 0 : stg_load + 1;

        const uint32_t stga = sbase + stg * STAGE_SZ;
#pragma unroll
        for (int step = 0; step < 4; step++) {
            uint32_t areg[2][4], breg[5][4];
#pragma unroll
            for (int mt = 0; mt < 2; mt++)
                LDSM4(areg[mt], stga + a_lane + mt * 16 * PITCH + step * 32);
#pragma unroll
            for (int nn = 0; nn < 5; nn++)
                LDSM4(breg[nn], stga + b_lane + nn * 16 * PITCH + step * 32);
#pragma unroll
            for (int mt = 0; mt < 2; mt++)
#pragma unroll
                for (int nt = 0; nt < 10; nt++)
                    MMA16816(c[mt][nt], areg[mt], breg[nt >> 1][(nt & 1) * 2],
                             breg[nt >> 1][(nt & 1) * 2 + 1]);
        }
        stg = (stg + 1 == 3) ? 0 : stg + 1;
    }
    __syncthreads();       // compute done; smem reused for C

    // ---- store C tile to smem: [128][CPITCH] floats ----
    float* C  = (float*)smem;
    float* RM = (float*)(smem + 128 * CPITCH * 4);   // [128][40] row maxes
    float* CM = RM + 128 * 40;                       // [8][320] col maxes
#pragma unroll
    for (int mt = 0; mt < 2; mt++)
#pragma unroll
        for (int nt = 0; nt < 10; nt++) {
            int row = wm * 32 + mt * 16 + (lane >> 2);
            int col = wn * 80 + nt * 8 + (lane & 3) * 2;
            *(float2*)&C[row * CPITCH + col]       = make_float2(c[mt][nt][0], c[mt][nt][1]);
            *(float2*)&C[(row + 8) * CPITCH + col] = make_float2(c[mt][nt][2], c[mt][nt][3]);
        }
    __syncthreads();

    const int nmb = g_mN[ib], njb = g_nN[jb];

    // ---- row part: per row, per j-batch: max over w<sl (+0 iff sl<37) ----
    if (tid < 128) {
        const float* Cr = &C[tid * CPITCH];
        for (int js = 0; js < njb; js++) {
            int cs = g_nCS[jb * 40 + js], sl = g_nSL[jb * 40 + js];
            float m = Cr[cs];
            for (int w = 1; w < sl; w++) m = fmaxf(m, Cr[cs + w]);
            if (sl < 37) m = fmaxf(m, 0.0f);
            RM[tid * 40 + js] = m;
        }
    }
    // ---- col part: per col, per m-batch: max over r<il (+0 iff il<49) ----
    if (tid < 320) {
        for (int ms = 0; ms < nmb; ms++) {
            int rs = g_mRS[ib * 8 + ms], il = g_mIL[ib * 8 + ms];
            float m = C[rs * CPITCH + tid];
            for (int r = 1; r < il; r++) m = fmaxf(m, C[(rs + r) * CPITCH + tid]);
            if (il < 49) m = fmaxf(m, 0.0f);
            CM[ms * 320 + tid] = m;
        }
    }
    __syncthreads();

    // ---- per-pair reduction & output ----
    if (tid < nmb * njb) {
        int ms = tid / njb, js = tid - ms * njb;
        int rs = g_mRS[ib * 8 + ms], il = g_mIL[ib * 8 + ms];
        int cs = g_nCS[jb * 40 + js], sl = g_nSL[jb * 40 + js];
        float sum = 0.0f;
        for (int r = 0; r < il; r++) sum += RM[(rs + r) * 40 + js];
        for (int w = 0; w < sl; w++) sum += CM[ms * 320 + cs + w];
        out[g_mB[ib * 8 + ms] * NBATCH + g_nB[jb * 40 + js]] = sum;
    }
}

extern "C" void kernel_launch(void* const* d_in, const int* in_sizes, int n_in,
                              void* d_out, int out_size) {
    (void)in_sizes; (void)n_in; (void)out_size;
    const float* im   = (const float*)d_in[0];
    const float* s    = (const float*)d_in[1];
    const int* im_len = (const int*)d_in[2];
    const int* s_len  = (const int*)d_in[3];
    float* out = (float*)d_out;

    plan_kernel<<<1, 128>>>(im_len, s_len);
    conv_kernel<<<6656, 256>>>(im, s, im_len, s_len);

    cudaFuncSetAttribute(align_gemm_kernel,
                         cudaFuncAttributeMaxDynamicSharedMemorySize, SMEM_BYTES);
    dim3 grid(16, 64);
    align_gemm_kernel<<<grid, 512, SMEM_BYTES>>>(im_len, s_len, out);
}

// round 12
// speedup vs baseline: 2.0430x; 1.0923x over previous
#include <cuda_runtime.h>
#include <cuda_fp16.h>
#include <cstdint>

// Problem: B=128, L_IM=50, L_S=40, D=1024
// im = im_set[:,1:,:]  -> il = im_len-1 valid rows (9..49)
// s  = s_seq[:,1:-2,:] -> sl = s_len-3  valid rows (7..37)
// Batches are bin-packed (whole) into dense GEMM tiles:
//   M: ceil(il/16) x 16-row fragments, 8 per 128-row tile  (<= 64 tiles)
//   N: ceil(sl/8)  x 8-col blocks,   40 per 320-col tile  (<= 16 tiles)
// Mainloop fully dense; pad rows/cols inside fragments are exact zeros (zfill).
#define NBATCH 128
#define DDIM   1024
#define AROWS  64
#define SROWS  40

__device__ __align__(1024) __half g_A[(size_t)NBATCH * AROWS * DDIM];  // 16 MB
__device__ __align__(1024) __half g_S[(size_t)NBATCH * SROWS * DDIM];  // 10 MB

// ---- packing plan ----
__device__ int g_TM, g_TN;
__device__ int g_fB[64 * 8],  g_fR[64 * 8];    // M tile fragment -> batch, row base
__device__ int g_mN[64], g_mB[64 * 8], g_mRS[64 * 8], g_mIL[64 * 8];
__device__ int g_bJ[16 * 40], g_bW[16 * 40];   // N tile block -> batch, w base
__device__ int g_nN[16], g_nB[16 * 40], g_nCS[16 * 40], g_nSL[16 * 40];

// ---------------- helpers ----------------
__device__ __forceinline__ uint32_t smem_u32(const void* p) {
    uint32_t a;
    asm("{ .reg .u64 t; cvta.to.shared.u64 t, %1; cvt.u32.u64 %0, t; }" : "=r"(a) : "l"(p));
    return a;
}

#define CP_ASYNC16Z(dst, src, sz) \
    asm volatile("cp.async.cg.shared.global [%0], [%1], 16, %2;" \
                 :: "r"(dst), "l"(src), "r"(sz))
#define CP_COMMIT() asm volatile("cp.async.commit_group;" ::: "memory")
#define CP_WAIT1()  asm volatile("cp.async.wait_group 1;" ::: "memory")

#define LDSM4(r, addr) \
    asm volatile("ldmatrix.sync.aligned.m8n8.x4.shared.b16 {%0,%1,%2,%3}, [%4];" \
                 : "=r"((r)[0]), "=r"((r)[1]), "=r"((r)[2]), "=r"((r)[3]) : "r"(addr))

#define MMA16816(c, a, b0, b1) \
    asm volatile("mma.sync.aligned.m16n8k16.row.col.f32.f16.f16.f32 " \
                 "{%0,%1,%2,%3},{%4,%5,%6,%7},{%8,%9},{%0,%1,%2,%3};" \
                 : "+f"((c)[0]), "+f"((c)[1]), "+f"((c)[2]), "+f"((c)[3]) \
                 : "r"((a)[0]), "r"((a)[1]), "r"((a)[2]), "r"((a)[3]), "r"(b0), "r"(b1))

// ------------- planner: parallel class-rank + register-chain serial walk -------------
__global__ void plan_kernel(const int* __restrict__ im_len, const int* __restrict__ s_len) {
    __shared__ int ordM[NBATCH], ordN[NBATCH];     // ordered batch index
    __shared__ int ovM[NBATCH],  ovN[NBATCH];      // ordered valid-lengths
    __shared__ int wcM[4][5], wcN[4][6];           // [warp][class]
    __shared__ int s_fB[64 * 8], s_fR[64 * 8];
    __shared__ int s_mN[64], s_mB[64 * 8], s_mRS[64 * 8], s_mIL[64 * 8];
    __shared__ int s_bJ[16 * 40], s_bW[16 * 40];
    __shared__ int s_nN[16], s_nB[16 * 40], s_nCS[16 * 40], s_nSL[16 * 40];
    __shared__ int s_TM, s_TN;
    const int t = threadIdx.x, w = t >> 5, ln = t & 31;
    const uint32_t lmask = (1u << ln) - 1u;

    int vI = im_len[t] - 1;  vI = vI < 1 ? 1 : (vI > 49 ? 49 : vI);
    int vS = s_len[t] - 3;   vS = vS < 1 ? 1 : (vS > 37 ? 37 : vS);
    const int frM = (vI + 15) >> 4;   // 1..4
    const int frN = (vS + 7) >> 3;    // 1..5

    int rkM = 0, rkN = 0;
#pragma unroll
    for (int c = 1; c <= 4; c++) {
        uint32_t b = __ballot_sync(0xffffffffu, frM == c);
        if (frM == c) rkM = __popc(b & lmask);
        if (ln == 0) wcM[w][c] = __popc(b);
    }
#pragma unroll
    for (int c = 1; c <= 5; c++) {
        uint32_t b = __ballot_sync(0xffffffffu, frN == c);
        if (frN == c) rkN = __popc(b & lmask);
        if (ln == 0) wcN[w][c] = __popc(b);
    }
    for (int k = t; k < 64 * 8; k += 128)  { s_fB[k] = -1; s_fR[k] = 0; s_mB[k] = 0; s_mRS[k] = 0; s_mIL[k] = 1; }
    for (int k = t; k < 16 * 40; k += 128) { s_bJ[k] = -1; s_bW[k] = 0; s_nB[k] = 0; s_nCS[k] = 0; s_nSL[k] = 1; }
    if (t < 64) s_mN[t] = 0;
    if (t < 16) s_nN[t] = 0;
    __syncthreads();

    // ordered position: classes DESCENDING, index ascending within class
    {
        int base = 0;
#pragma unroll
        for (int c = 4; c > 0; c--)
            if (c > frM) base += wcM[0][c] + wcM[1][c] + wcM[2][c] + wcM[3][c];
        for (int ww = 0; ww < 4; ww++) if (ww < w) base += wcM[ww][frM];
        ordM[base + rkM] = t;
        ovM[base + rkM]  = vI;
    }
    {
        int base = 0;
#pragma unroll
        for (int c = 5; c > 0; c--)
            if (c > frN) base += wcN[0][c] + wcN[1][c] + wcN[2][c] + wcN[3][c];
        for (int ww = 0; ww < 4; ww++) if (ww < w) base += wcN[ww][frN];
        ordN[base + rkN] = t;
        ovN[base + rkN]  = vS;
    }
    __syncthreads();

    if (t == 0) {                       // M walk: register-only serial chain
        int tm = 0, used = 0, slot = 0;
#pragma unroll 4
        for (int k = 0; k < NBATCH; k++) {
            int v = ovM[k], i = ordM[k];        // independent loads (pipelined)
            int fr = (v + 15) >> 4;
            if (used + fr > 8) { s_mN[tm] = slot; tm++; used = 0; slot = 0; }
            s_mB[tm * 8 + slot]  = i;
            s_mRS[tm * 8 + slot] = used * 16;
            s_mIL[tm * 8 + slot] = v;
            for (int q = 0; q < fr; q++) {
                s_fB[tm * 8 + used + q] = i;
                s_fR[tm * 8 + used + q] = q * 16;
            }
            used += fr; slot++;
        }
        s_mN[tm] = slot;
        s_TM = tm + 1;
    }
    if (t == 32) {                      // N walk: different warp -> truly parallel
        int tn = 0, used = 0, slot = 0;
#pragma unroll 4
        for (int k = 0; k < NBATCH; k++) {
            int v = ovN[k], j = ordN[k];
            int bl = (v + 7) >> 3;
            if (used + bl > 40) { s_nN[tn] = slot; tn++; used = 0; slot = 0; }
            s_nB[tn * 40 + slot]  = j;
            s_nCS[tn * 40 + slot] = used * 8;
            s_nSL[tn * 40 + slot] = v;
            for (int q = 0; q < bl; q++) {
                s_bJ[tn * 40 + used + q] = j;
                s_bW[tn * 40 + used + q] = q * 8;
            }
            used += bl; slot++;
        }
        s_nN[tn] = slot;
        s_TN = tn + 1;
    }
    __syncthreads();

    for (int k = t; k < 64 * 8; k += 128) {
        g_fB[k] = s_fB[k];  g_fR[k] = s_fR[k];
        g_mB[k] = s_mB[k];  g_mRS[k] = s_mRS[k];  g_mIL[k] = s_mIL[k];
    }
    for (int k = t; k < 16 * 40; k += 128) {
        g_bJ[k] = s_bJ[k];  g_bW[k] = s_bW[k];
        g_nB[k] = s_nB[k];  g_nCS[k] = s_nCS[k];  g_nSL[k] = s_nSL[k];
    }
    if (t < 64) g_mN[t] = s_mN[t];
    if (t < 16) g_nN[t] = s_nN[t];
    if (t == 0) g_TM = s_TM;
    if (t == 32) g_TN = s_TN;
}

// ------------- merged conversion: fp32 -> fp16, valid rows only -------------
__global__ void conv_kernel(const float* __restrict__ im, const float* __restrict__ s,
                            const int* __restrict__ im_len, const int* __restrict__ s_len) {
    int b = blockIdx.x;
    if (b < 4096) {                                     // A path
        int u = b * 256 + threadIdx.x;                  // < 128*64*128
        int i  = u >> 13;
        int r  = (u >> 7) & 63;
        int d0 = (u & 127) << 3;
        int L = im_len[i] - 1;
        if (r >= L || r >= 49) return;
        const float* src = im + ((size_t)i * 50 + r + 1) * DDIM + d0;
        float4 f0 = ((const float4*)src)[0];
        float4 f1 = ((const float4*)src)[1];
        union { uint4 v; __half2 h[4]; } pk;
        pk.h[0] = __float22half2_rn(make_float2(f0.x, f0.y));
        pk.h[1] = __float22half2_rn(make_float2(f0.z, f0.w));
        pk.h[2] = __float22half2_rn(make_float2(f1.x, f1.y));
        pk.h[3] = __float22half2_rn(make_float2(f1.z, f1.w));
        *((uint4*)(g_A + ((size_t)i * AROWS + r) * DDIM + d0)) = pk.v;
    } else {                                            // S path
        int u = (b - 4096) * 256 + threadIdx.x;         // < 128*40*128
        int i   = u / (SROWS * 128);
        int rem = u - i * (SROWS * 128);
        int r  = rem >> 7;
        int d0 = (rem & 127) << 3;
        int L = s_len[i] - 3;
        if (r >= L || r >= 37) return;
        const float* src = s + ((size_t)i * 40 + r + 1) * DDIM + d0;
        float4 f0 = ((const float4*)src)[0];
        float4 f1 = ((const float4*)src)[1];
        union { uint4 v; __half2 h[4]; } pk;
        pk.h[0] = __float22half2_rn(make_float2(f0.x, f0.y));
        pk.h[1] = __float22half2_rn(make_float2(f0.z, f0.w));
        pk.h[2] = __float22half2_rn(make_float2(f1.x, f1.y));
        pk.h[3] = __float22half2_rn(make_float2(f1.z, f1.w));
        *((uint4*)(g_S + ((size_t)i * SROWS + r) * DDIM + d0)) = pk.v;
    }
}

// ------------- dense packed GEMM + per-pair masked max/sum epilogue -------------
// CTA: 512 threads, tile M=128 x N=320, K=1024 in 16 chunks of 64.
// Warp grid 4(m) x 4(n): warp tile 32 x 80. ONE barrier per k-chunk.
#define PITCH     144
#define ASTAGE    18432              // 128*144
#define STAGE_SZ  64512              // ASTAGE + 320*144
#define CPITCH    326                // even -> float2-aligned; 326*4 % 128 = 24
#define SMEM_BYTES 197632            // C (128*CPITCH*4) + RM (128*40*4) + CM (8*320*4)

__global__ void __launch_bounds__(512, 1) align_gemm_kernel(
        const int* __restrict__ im_len, const int* __restrict__ s_len,
        float* __restrict__ out) {
    const int jb = blockIdx.x;       // N tile
    const int ib = blockIdx.y;       // M tile
    if (ib >= g_TM || jb >= g_TN) return;

    extern __shared__ __align__(16) char smem[];
    const int tid  = threadIdx.x;
    const int lane = tid & 31;
    const int wid  = tid >> 5;
    const int wm   = wid & 3;        // M offset wm*32
    const int wn   = wid >> 2;       // N offset wn*80
    const uint32_t sbase = smem_u32(smem) + 128;

    // ---- per-thread load setup (advance src by 128B per kt) ----
    const char* srcA[2]; uint32_t dstA[2], szA[2];
#pragma unroll
    for (int q = 0; q < 2; q++) {
        int idx = tid + q * 512, row = idx >> 3, cc = idx & 7;
        int f = row >> 4;
        int b = g_fB[ib * 8 + f];
        int r = g_fR[ib * 8 + f] + (row & 15);
        int il = (b >= 0) ? (__ldg(&im_len[b]) - 1) : 0;
        szA[q] = (b >= 0 && r < il) ? 16u : 0u;
        int bs = b < 0 ? 0 : b;
        srcA[q] = (const char*)(g_A + ((size_t)bs * AROWS + r) * DDIM) + cc * 16;
        dstA[q] = sbase + row * PITCH + cc * 16;
    }
    const char* srcB[5]; uint32_t dstB[5], szB[5];
#pragma unroll
    for (int q = 0; q < 5; q++) {
        int idx = tid + q * 512, row = idx >> 3, cc = idx & 7;
        int blk = row >> 3;
        int j = g_bJ[jb * 40 + blk];
        int w = g_bW[jb * 40 + blk] + (row & 7);
        int sl = (j >= 0) ? (__ldg(&s_len[j]) - 3) : 0;
        szB[q] = (j >= 0 && w < sl) ? 16u : 0u;
        int js = j < 0 ? 0 : j;
        srcB[q] = (const char*)(g_S + ((size_t)js * SROWS + w) * DDIM) + cc * 16;
        dstB[q] = sbase + ASTAGE + row * PITCH + cc * 16;
    }

    // ldmatrix lane addresses
    const int quad = lane >> 3, r8 = lane & 7;
    const uint32_t a_lane = (uint32_t)((wm * 32 + (quad & 1) * 8 + r8) * PITCH
                                       + (quad >> 1) * 16);
    const uint32_t b_lane = (uint32_t)(ASTAGE
                                       + (wn * 80 + (quad >> 1) * 8 + r8) * PITCH
                                       + (quad & 1) * 16);

    float c[2][10][4];
#pragma unroll
    for (int mt = 0; mt < 2; mt++)
#pragma unroll
        for (int nt = 0; nt < 10; nt++)
#pragma unroll
            for (int q = 0; q < 4; q++) c[mt][nt][q] = 0.0f;

    // ---- prologue: 2 stages in flight ----
#pragma unroll
    for (int p = 0; p < 2; p++) {
        uint32_t so = (uint32_t)(p * STAGE_SZ), ko = (uint32_t)(p * 128);
#pragma unroll
        for (int q = 0; q < 2; q++) CP_ASYNC16Z(dstA[q] + so, srcA[q] + ko, szA[q]);
#pragma unroll
        for (int q = 0; q < 5; q++) CP_ASYNC16Z(dstB[q] + so, srcB[q] + ko, szB[q]);
        CP_COMMIT();
    }

    int stg = 0, stg_load = 2;
#pragma unroll 1
    for (int kt = 0; kt < 16; kt++) {
        CP_WAIT1();            // loads for kt complete (only kt+1's group may pend)
        __syncthreads();       // data visible; stage (kt-1)%3 == (kt+2)%3 consumer-free

        if (kt + 2 < 16) {     // prefetch kt+2 BEFORE compute -> overlaps this kt
            uint32_t so = (uint32_t)(stg_load * STAGE_SZ), ko = (uint32_t)((kt + 2) * 128);
#pragma unroll
            for (int q = 0; q < 2; q++) CP_ASYNC16Z(dstA[q] + so, srcA[q] + ko, szA[q]);
#pragma unroll
            for (int q = 0; q < 5; q++) CP_ASYNC16Z(dstB[q] + so, srcB[q] + ko, szB[q]);
        }
        CP_COMMIT();           // empty commits at tail keep wait_group accounting
        stg_load = (stg_load + 1 == 3) ? 0 : stg_load + 1;

        const uint32_t stga = sbase + stg * STAGE_SZ;
#pragma unroll
        for (int step = 0; step < 4; step++) {
            uint32_t areg[2][4], breg[5][4];
#pragma unroll
            for (int mt = 0; mt < 2; mt++)
                LDSM4(areg[mt], stga + a_lane + mt * 16 * PITCH + step * 32);
#pragma unroll
            for (int nn = 0; nn < 5; nn++)
                LDSM4(breg[nn], stga + b_lane + nn * 16 * PITCH + step * 32);
#pragma unroll
            for (int mt = 0; mt < 2; mt++)
#pragma unroll
                for (int nt = 0; nt < 10; nt++)
                    MMA16816(c[mt][nt], areg[mt], breg[nt >> 1][(nt & 1) * 2],
                             breg[nt >> 1][(nt & 1) * 2 + 1]);
        }
        stg = (stg + 1 == 3) ? 0 : stg + 1;
    }
    __syncthreads();       // compute done; smem reused for C

    // ---- store C tile to smem: [128][CPITCH] floats ----
    float* C  = (float*)smem;
    float* RM = (float*)(smem + 128 * CPITCH * 4);   // [128][40] row maxes
    float* CM = RM + 128 * 40;                       // [8][320] col maxes
#pragma unroll
    for (int mt = 0; mt < 2; mt++)
#pragma unroll
        for (int nt = 0; nt < 10; nt++) {
            int row = wm * 32 + mt * 16 + (lane >> 2);
            int col = wn * 80 + nt * 8 + (lane & 3) * 2;
            *(float2*)&C[row * CPITCH + col]       = make_float2(c[mt][nt][0], c[mt][nt][1]);
            *(float2*)&C[(row + 8) * CPITCH + col] = make_float2(c[mt][nt][2], c[mt][nt][3]);
        }
    __syncthreads();

    const int nmb = g_mN[ib], njb = g_nN[jb];

    // ---- row part: per row, per j-batch: max over w<sl (+0 iff sl<37) ----
    if (tid < 128) {
        const float* Cr = &C[tid * CPITCH];
        for (int js = 0; js < njb; js++) {
            int cs = g_nCS[jb * 40 + js], sl = g_nSL[jb * 40 + js];
            float m = Cr[cs];
            for (int w = 1; w < sl; w++) m = fmaxf(m, Cr[cs + w]);
            if (sl < 37) m = fmaxf(m, 0.0f);
            RM[tid * 40 + js] = m;
        }
    }
    // ---- col part: per col, per m-batch: max over r<il (+0 iff il<49) ----
    if (tid < 320) {
        for (int ms = 0; ms < nmb; ms++) {
            int rs = g_mRS[ib * 8 + ms], il = g_mIL[ib * 8 + ms];
            float m = C[rs * CPITCH + tid];
            for (int r = 1; r < il; r++) m = fmaxf(m, C[(rs + r) * CPITCH + tid]);
            if (il < 49) m = fmaxf(m, 0.0f);
            CM[ms * 320 + tid] = m;
        }
    }
    __syncthreads();

    // ---- per-pair reduction & output ----
    if (tid < nmb * njb) {
        int ms = tid / njb, js = tid - ms * njb;
        int rs = g_mRS[ib * 8 + ms], il = g_mIL[ib * 8 + ms];
        int cs = g_nCS[jb * 40 + js], sl = g_nSL[jb * 40 + js];
        float sum = 0.0f;
        for (int r = 0; r < il; r++) sum += RM[(rs + r) * 40 + js];
        for (int w = 0; w < sl; w++) sum += CM[ms * 320 + cs + w];
        out[g_mB[ib * 8 + ms] * NBATCH + g_nB[jb * 40 + js]] = sum;
    }
}

extern "C" void kernel_launch(void* const* d_in, const int* in_sizes, int n_in,
                              void* d_out, int out_size) {
    (void)in_sizes; (void)n_in; (void)out_size;
    const float* im   = (const float*)d_in[0];
    const float* s    = (const float*)d_in[1];
    const int* im_len = (const int*)d_in[2];
    const int* s_len  = (const int*)d_in[3];
    float* out = (float*)d_out;

    plan_kernel<<<1, 128>>>(im_len, s_len);
    conv_kernel<<<6656, 256>>>(im, s, im_len, s_len);

    cudaFuncSetAttribute(align_gemm_kernel,
                         cudaFuncAttributeMaxDynamicSharedMemorySize, SMEM_BYTES);
    dim3 grid(16, 64);
    align_gemm_kernel<<<grid, 512, SMEM_BYTES>>>(im_len, s_len, out);
}

// round 13
// speedup vs baseline: 2.2356x; 1.0943x over previous
#include <cuda_runtime.h>
#include <cuda_fp16.h>
#include <cstdint>

// Problem: B=128, L_IM=50, L_S=40, D=1024
// im = im_set[:,1:,:]  -> il = im_len-1 valid rows (9..49)
// s  = s_seq[:,1:-2,:] -> sl = s_len-3  valid rows (7..37)
// Batches are bin-packed (whole) into dense GEMM tiles:
//   M: ceil(il/16) x 16-row fragments, 8 per 128-row tile  (<= 64 tiles)
//   N: ceil(sl/8)  x 8-col blocks,   40 per 320-col tile  (<= 16 tiles)
// Packing is computed in CLOSED FORM per thread (no serial walk); result is
// bit-identical to first-fit over class-descending, index-ascending order.
#define NBATCH 128
#define DDIM   1024
#define AROWS  64
#define SROWS  40

__device__ __align__(1024) __half g_A[(size_t)NBATCH * AROWS * DDIM];  // 16 MB
__device__ __align__(1024) __half g_S[(size_t)NBATCH * SROWS * DDIM];  // 10 MB

// ---- packing plan ----
__device__ int g_TM, g_TN;
__device__ int g_fB[64 * 8],  g_fR[64 * 8];    // M tile fragment -> batch, row base
__device__ int g_mN[64], g_mB[64 * 8], g_mRS[64 * 8], g_mIL[64 * 8];
__device__ int g_bJ[16 * 40], g_bW[16 * 40];   // N tile block -> batch, w base
__device__ int g_nN[16], g_nB[16 * 40], g_nCS[16 * 40], g_nSL[16 * 40];

// ---------------- helpers ----------------
__device__ __forceinline__ uint32_t smem_u32(const void* p) {
    uint32_t a;
    asm("{ .reg .u64 t; cvta.to.shared.u64 t, %1; cvt.u32.u64 %0, t; }" : "=r"(a) : "l"(p));
    return a;
}

#define CP_ASYNC16Z(dst, src, sz) \
    asm volatile("cp.async.cg.shared.global [%0], [%1], 16, %2;" \
                 :: "r"(dst), "l"(src), "r"(sz))
#define CP_COMMIT() asm volatile("cp.async.commit_group;" ::: "memory")
#define CP_WAIT1()  asm volatile("cp.async.wait_group 1;" ::: "memory")

#define LDSM4(r, addr) \
    asm volatile("ldmatrix.sync.aligned.m8n8.x4.shared.b16 {%0,%1,%2,%3}, [%4];" \
                 : "=r"((r)[0]), "=r"((r)[1]), "=r"((r)[2]), "=r"((r)[3]) : "r"(addr))

#define MMA16816(c, a, b0, b1) \
    asm volatile("mma.sync.aligned.m16n8k16.row.col.f32.f16.f16.f32 " \
                 "{%0,%1,%2,%3},{%4,%5,%6,%7},{%8,%9},{%0,%1,%2,%3};" \
                 : "+f"((c)[0]), "+f"((c)[1]), "+f"((c)[2]), "+f"((c)[3]) \
                 : "r"((a)[0]), "r"((a)[1]), "r"((a)[2]), "r"((a)[3]), "r"(b0), "r"(b1))

// Closed-form first-fit over classes DESCENDING (cmax..1), rank r within class.
// cap = tile capacity (fragments). Returns this item's (tile, off, slot) and
// final (t0,u0,s0) state -> tile count. Identical to the serial walk.
struct PackPos { int tile, off, slot, ntiles; };
__device__ __forceinline__ PackPos pack_pos(int myClass, int myRank,
                                            const int* cnt, int cmax, int cap) {
    int t0 = 0, u0 = 0, s0 = 0;
    PackPos p; p.tile = 0; p.off = 0; p.slot = 0;
    for (int c = cmax; c >= 1; c--) {
        int n  = cnt[c];
        int k0 = (cap - u0) / c;        // items fitting in current tile
        int kc = cap / c;               // items per fresh tile
        if (c == myClass) {
            if (myRank < k0) { p.tile = t0; p.off = u0 + myRank * c; p.slot = s0 + myRank; }
            else {
                int rp = myRank - k0;
                p.tile = t0 + 1 + rp / kc;
                p.off  = (rp % kc) * c;
                p.slot = rp % kc;
            }
        }
        if (n > 0) {
            if (n <= k0) { u0 += n * c; s0 += n; }
            else {
                int rp   = n - k0;
                int full = (rp - 1) / kc;
                int last = (rp - 1) % kc + 1;
                t0 += 1 + full;
                u0 = last * c;
                s0 = last;
            }
        }
    }
    p.ntiles = t0 + 1;
    return p;
}

// ------------- planner: fully parallel (no serial walk) -------------
__global__ void plan_kernel(const int* __restrict__ im_len, const int* __restrict__ s_len) {
    __shared__ int wcM[4][5], wcN[4][6];           // [warp][class]
    __shared__ int s_fB[64 * 8], s_fR[64 * 8];
    __shared__ int s_mN[64], s_mB[64 * 8], s_mRS[64 * 8], s_mIL[64 * 8];
    __shared__ int s_bJ[16 * 40], s_bW[16 * 40];
    __shared__ int s_nN[16], s_nB[16 * 40], s_nCS[16 * 40], s_nSL[16 * 40];
    const int t = threadIdx.x, w = t >> 5, ln = t & 31;
    const uint32_t lmask = (1u << ln) - 1u;

    int vI = im_len[t] - 1;  vI = vI < 1 ? 1 : (vI > 49 ? 49 : vI);
    int vS = s_len[t] - 3;   vS = vS < 1 ? 1 : (vS > 37 ? 37 : vS);
    const int frM = (vI + 15) >> 4;   // class 1..4
    const int frN = (vS + 7) >> 3;    // class 1..5

    int rkM = 0, rkN = 0;             // rank within class, within warp
#pragma unroll
    for (int c = 1; c <= 4; c++) {
        uint32_t b = __ballot_sync(0xffffffffu, frM == c);
        if (frM == c) rkM = __popc(b & lmask);
        if (ln == 0) wcM[w][c] = __popc(b);
    }
#pragma unroll
    for (int c = 1; c <= 5; c++) {
        uint32_t b = __ballot_sync(0xffffffffu, frN == c);
        if (frN == c) rkN = __popc(b & lmask);
        if (ln == 0) wcN[w][c] = __popc(b);
    }
    for (int k = t; k < 64 * 8; k += 128)  { s_fB[k] = -1; s_fR[k] = 0; s_mB[k] = 0; s_mRS[k] = 0; s_mIL[k] = 1; }
    for (int k = t; k < 16 * 40; k += 128) { s_bJ[k] = -1; s_bW[k] = 0; s_nB[k] = 0; s_nCS[k] = 0; s_nSL[k] = 1; }
    if (t < 64) s_mN[t] = 0;
    if (t < 16) s_nN[t] = 0;
    __syncthreads();

    // global class counts + global rank within class
    int cntM[5], cntN[6];
#pragma unroll
    for (int c = 1; c <= 4; c++) cntM[c] = wcM[0][c] + wcM[1][c] + wcM[2][c] + wcM[3][c];
#pragma unroll
    for (int c = 1; c <= 5; c++) cntN[c] = wcN[0][c] + wcN[1][c] + wcN[2][c] + wcN[3][c];
    for (int ww = 0; ww < 4; ww++) {
        if (ww < w) { rkM += wcM[ww][frM]; rkN += wcN[ww][frN]; }
    }

    // closed-form position (all threads, pure registers)
    PackPos pM = pack_pos(frM, rkM, cntM, 4, 8);
    PackPos pN = pack_pos(frN, rkN, cntN, 5, 40);

    // write plan entries (each thread owns its batch)
    s_mB[pM.tile * 8 + pM.slot]  = t;
    s_mRS[pM.tile * 8 + pM.slot] = pM.off * 16;
    s_mIL[pM.tile * 8 + pM.slot] = vI;
    atomicAdd(&s_mN[pM.tile], 1);
    for (int q = 0; q < frM; q++) {
        s_fB[pM.tile * 8 + pM.off + q] = t;
        s_fR[pM.tile * 8 + pM.off + q] = q * 16;
    }
    s_nB[pN.tile * 40 + pN.slot]  = t;
    s_nCS[pN.tile * 40 + pN.slot] = pN.off * 8;
    s_nSL[pN.tile * 40 + pN.slot] = vS;
    atomicAdd(&s_nN[pN.tile], 1);
    for (int q = 0; q < frN; q++) {
        s_bJ[pN.tile * 40 + pN.off + q] = t;
        s_bW[pN.tile * 40 + pN.off + q] = q * 8;
    }
    __syncthreads();

    for (int k = t; k < 64 * 8; k += 128) {
        g_fB[k] = s_fB[k];  g_fR[k] = s_fR[k];
        g_mB[k] = s_mB[k];  g_mRS[k] = s_mRS[k];  g_mIL[k] = s_mIL[k];
    }
    for (int k = t; k < 16 * 40; k += 128) {
        g_bJ[k] = s_bJ[k];  g_bW[k] = s_bW[k];
        g_nB[k] = s_nB[k];  g_nCS[k] = s_nCS[k];  g_nSL[k] = s_nSL[k];
    }
    if (t < 64) g_mN[t] = s_mN[t];
    if (t < 16) g_nN[t] = s_nN[t];
    if (t == 0) { g_TM = pM.ntiles; g_TN = pN.ntiles; }
}

// ------------- merged conversion: fp32 -> fp16, valid rows only -------------
__global__ void conv_kernel(const float* __restrict__ im, const float* __restrict__ s,
                            const int* __restrict__ im_len, const int* __restrict__ s_len) {
    int b = blockIdx.x;
    if (b < 4096) {                                     // A path
        int u = b * 256 + threadIdx.x;                  // < 128*64*128
        int i  = u >> 13;
        int r  = (u >> 7) & 63;
        int d0 = (u & 127) << 3;
        int L = im_len[i] - 1;
        if (r >= L || r >= 49) return;
        const float* src = im + ((size_t)i * 50 + r + 1) * DDIM + d0;
        float4 f0 = ((const float4*)src)[0];
        float4 f1 = ((const float4*)src)[1];
        union { uint4 v; __half2 h[4]; } pk;
        pk.h[0] = __float22half2_rn(make_float2(f0.x, f0.y));
        pk.h[1] = __float22half2_rn(make_float2(f0.z, f0.w));
        pk.h[2] = __float22half2_rn(make_float2(f1.x, f1.y));
        pk.h[3] = __float22half2_rn(make_float2(f1.z, f1.w));
        *((uint4*)(g_A + ((size_t)i * AROWS + r) * DDIM + d0)) = pk.v;
    } else {                                            // S path
        int u = (b - 4096) * 256 + threadIdx.x;         // < 128*40*128
        int i   = u / (SROWS * 128);
        int rem = u - i * (SROWS * 128);
        int r  = rem >> 7;
        int d0 = (rem & 127) << 3;
        int L = s_len[i] - 3;
        if (r >= L || r >= 37) return;
        const float* src = s + ((size_t)i * 40 + r + 1) * DDIM + d0;
        float4 f0 = ((const float4*)src)[0];
        float4 f1 = ((const float4*)src)[1];
        union { uint4 v; __half2 h[4]; } pk;
        pk.h[0] = __float22half2_rn(make_float2(f0.x, f0.y));
        pk.h[1] = __float22half2_rn(make_float2(f0.z, f0.w));
        pk.h[2] = __float22half2_rn(make_float2(f1.x, f1.y));
        pk.h[3] = __float22half2_rn(make_float2(f1.z, f1.w));
        *((uint4*)(g_S + ((size_t)i * SROWS + r) * DDIM + d0)) = pk.v;
    }
}

// ------------- dense packed GEMM + per-pair masked max/sum epilogue -------------
// CTA: 512 threads, tile M=128 x N=320, K=1024 in 16 chunks of 64.
// Warp grid 4(m) x 4(n): warp tile 32 x 80. ONE barrier per k-chunk.
#define PITCH     144
#define ASTAGE    18432              // 128*144
#define STAGE_SZ  64512              // ASTAGE + 320*144
#define CPITCH    326                // even -> float2-aligned; 326*4 % 128 = 24
#define SMEM_BYTES 197632            // C (128*CPITCH*4) + RM (128*40*4) + CM (8*320*4)

__global__ void __launch_bounds__(512, 1) align_gemm_kernel(
        const int* __restrict__ im_len, const int* __restrict__ s_len,
        float* __restrict__ out) {
    const int jb = blockIdx.x;       // N tile
    const int ib = blockIdx.y;       // M tile
    if (ib >= g_TM || jb >= g_TN) return;

    extern __shared__ __align__(16) char smem[];
    const int tid  = threadIdx.x;
    const int lane = tid & 31;
    const int wid  = tid >> 5;
    const int wm   = wid & 3;        // M offset wm*32
    const int wn   = wid >> 2;       // N offset wn*80
    const uint32_t sbase = smem_u32(smem) + 128;

    // ---- per-thread load setup (advance src by 128B per kt) ----
    const char* srcA[2]; uint32_t dstA[2], szA[2];
#pragma unroll
    for (int q = 0; q < 2; q++) {
        int idx = tid + q * 512, row = idx >> 3, cc = idx & 7;
        int f = row >> 4;
        int b = g_fB[ib * 8 + f];
        int r = g_fR[ib * 8 + f] + (row & 15);
        int il = (b >= 0) ? (__ldg(&im_len[b]) - 1) : 0;
        szA[q] = (b >= 0 && r < il) ? 16u : 0u;
        int bs = b < 0 ? 0 : b;
        srcA[q] = (const char*)(g_A + ((size_t)bs * AROWS + r) * DDIM) + cc * 16;
        dstA[q] = sbase + row * PITCH + cc * 16;
    }
    const char* srcB[5]; uint32_t dstB[5], szB[5];
#pragma unroll
    for (int q = 0; q < 5; q++) {
        int idx = tid + q * 512, row = idx >> 3, cc = idx & 7;
        int blk = row >> 3;
        int j = g_bJ[jb * 40 + blk];
        int w = g_bW[jb * 40 + blk] + (row & 7);
        int sl = (j >= 0) ? (__ldg(&s_len[j]) - 3) : 0;
        szB[q] = (j >= 0 && w < sl) ? 16u : 0u;
        int js = j < 0 ? 0 : j;
        srcB[q] = (const char*)(g_S + ((size_t)js * SROWS + w) * DDIM) + cc * 16;
        dstB[q] = sbase + ASTAGE + row * PITCH + cc * 16;
    }

    // ldmatrix lane addresses
    const int quad = lane >> 3, r8 = lane & 7;
    const uint32_t a_lane = (uint32_t)((wm * 32 + (quad & 1) * 8 + r8) * PITCH
                                       + (quad >> 1) * 16);
    const uint32_t b_lane = (uint32_t)(ASTAGE
                                       + (wn * 80 + (quad >> 1) * 8 + r8) * PITCH
                                       + (quad & 1) * 16);

    float c[2][10][4];
#pragma unroll
    for (int mt = 0; mt < 2; mt++)
#pragma unroll
        for (int nt = 0; nt < 10; nt++)
#pragma unroll
            for (int q = 0; q < 4; q++) c[mt][nt][q] = 0.0f;

    // ---- prologue: 2 stages in flight ----
#pragma unroll
    for (int p = 0; p < 2; p++) {
        uint32_t so = (uint32_t)(p * STAGE_SZ), ko = (uint32_t)(p * 128);
#pragma unroll
        for (int q = 0; q < 2; q++) CP_ASYNC16Z(dstA[q] + so, srcA[q] + ko, szA[q]);
#pragma unroll
        for (int q = 0; q < 5; q++) CP_ASYNC16Z(dstB[q] + so, srcB[q] + ko, szB[q]);
        CP_COMMIT();
    }

    int stg = 0, stg_load = 2;
#pragma unroll 1
    for (int kt = 0; kt < 16; kt++) {
        CP_WAIT1();            // loads for kt complete (only kt+1's group may pend)
        __syncthreads();       // data visible; stage (kt-1)%3 == (kt+2)%3 consumer-free

        if (kt + 2 < 16) {     // prefetch kt+2 BEFORE compute -> overlaps this kt
            uint32_t so = (uint32_t)(stg_load * STAGE_SZ), ko = (uint32_t)((kt + 2) * 128);
#pragma unroll
            for (int q = 0; q < 2; q++) CP_ASYNC16Z(dstA[q] + so, srcA[q] + ko, szA[q]);
#pragma unroll
            for (int q = 0; q < 5; q++) CP_ASYNC16Z(dstB[q] + so, srcB[q] + ko, szB[q]);
        }
        CP_COMMIT();           // empty commits at tail keep wait_group accounting
        stg_load = (stg_load + 1 == 3) ? 0 : stg_load + 1;

        const uint32_t stga = sbase + stg * STAGE_SZ;
#pragma unroll
        for (int step = 0; step < 4; step++) {
            uint32_t areg[2][4], breg[5][4];
#pragma unroll
            for (int mt = 0; mt < 2; mt++)
                LDSM4(areg[mt], stga + a_lane + mt * 16 * PITCH + step * 32);
#pragma unroll
            for (int nn = 0; nn < 5; nn++)
                LDSM4(breg[nn], stga + b_lane + nn * 16 * PITCH + step * 32);
#pragma unroll
            for (int mt = 0; mt < 2; mt++)
#pragma unroll
                for (int nt = 0; nt < 10; nt++)
                    MMA16816(c[mt][nt], areg[mt], breg[nt >> 1][(nt & 1) * 2],
                             breg[nt >> 1][(nt & 1) * 2 + 1]);
        }
        stg = (stg + 1 == 3) ? 0 : stg + 1;
    }
    __syncthreads();       // compute done; smem reused for C

    // ---- store C tile to smem: [128][CPITCH] floats ----
    float* C  = (float*)smem;
    float* RM = (float*)(smem + 128 * CPITCH * 4);   // [128][40] row maxes
    float* CM = RM + 128 * 40;                       // [8][320] col maxes
#pragma unroll
    for (int mt = 0; mt < 2; mt++)
#pragma unroll
        for (int nt = 0; nt < 10; nt++) {
            int row = wm * 32 + mt * 16 + (lane >> 2);
            int col = wn * 80 + nt * 8 + (lane & 3) * 2;
            *(float2*)&C[row * CPITCH + col]       = make_float2(c[mt][nt][0], c[mt][nt][1]);
            *(float2*)&C[(row + 8) * CPITCH + col] = make_float2(c[mt][nt][2], c[mt][nt][3]);
        }
    __syncthreads();

    const int nmb = g_mN[ib], njb = g_nN[jb];

    // ---- row part: per row, per j-batch: max over w<sl (+0 iff sl<37) ----
    if (tid < 128) {
        const float* Cr = &C[tid * CPITCH];
        for (int js = 0; js < njb; js++) {
            int cs = g_nCS[jb * 40 + js], sl = g_nSL[jb * 40 + js];
            float m = Cr[cs];
            for (int w = 1; w < sl; w++) m = fmaxf(m, Cr[cs + w]);
            if (sl < 37) m = fmaxf(m, 0.0f);
            RM[tid * 40 + js] = m;
        }
    }
    // ---- col part: per col, per m-batch: max over r<il (+0 iff il<49) ----
    if (tid < 320) {
        for (int ms = 0; ms < nmb; ms++) {
            int rs = g_mRS[ib * 8 + ms], il = g_mIL[ib * 8 + ms];
            float m = C[rs * CPITCH + tid];
            for (int r = 1; r < il; r++) m = fmaxf(m, C[(rs + r) * CPITCH + tid]);
            if (il < 49) m = fmaxf(m, 0.0f);
            CM[ms * 320 + tid] = m;
        }
    }
    __syncthreads();

    // ---- per-pair reduction & output ----
    if (tid < nmb * njb) {
        int ms = tid / njb, js = tid - ms * njb;
        int rs = g_mRS[ib * 8 + ms], il = g_mIL[ib * 8 + ms];
        int cs = g_nCS[jb * 40 + js], sl = g_nSL[jb * 40 + js];
        float sum = 0.0f;
        for (int r = 0; r < il; r++) sum += RM[(rs + r) * 40 + js];
        for (int w = 0; w < sl; w++) sum += CM[ms * 320 + cs + w];
        out[g_mB[ib * 8 + ms] * NBATCH + g_nB[jb * 40 + js]] = sum;
    }
}

extern "C" void kernel_launch(void* const* d_in, const int* in_sizes, int n_in,
                              void* d_out, int out_size) {
    (void)in_sizes; (void)n_in; (void)out_size;
    const float* im   = (const float*)d_in[0];
    const float* s    = (const float*)d_in[1];
    const int* im_len = (const int*)d_in[2];
    const int* s_len  = (const int*)d_in[3];
    float* out = (float*)d_out;

    plan_kernel<<<1, 128>>>(im_len, s_len);
    conv_kernel<<<6656, 256>>>(im, s, im_len, s_len);

    cudaFuncSetAttribute(align_gemm_kernel,
                         cudaFuncAttributeMaxDynamicSharedMemorySize, SMEM_BYTES);
    dim3 grid(16, 64);
    align_gemm_kernel<<<grid, 512, SMEM_BYTES>>>(im_len, s_len, out);
}